// round 1
// baseline (speedup 1.0000x reference)
#include <cuda_runtime.h>
#include <math.h>

#define N_NODES 16000
#define N_EDGES 256000
#define DIM 256
#define HEADS 8
#define DH 32
#define HID 1024
#define LN_CNT (N_NODES * DIM)
#define LN_EPS 1e-5f
#define RSQRT_DH 0.17677669529663687f

// ---------------- scratch (static device globals; no allocation) -------------
__device__ float    g_e[(size_t)N_EDGES * DIM];      // 262 MB edge projection
__device__ float    g_q[N_NODES * DIM];
__device__ float    g_k[N_NODES * DIM];
__device__ float    g_v[N_NODES * DIM];
__device__ float    g_out[N_NODES * DIM];            // skip + aggregated messages / ffn out
__device__ float    g_y[N_NODES * DIM];              // post-LN1 activations
__device__ float    g_x[N_NODES * DIM];              // block output
__device__ float    g_h[N_NODES * HID];              // ffn hidden
__device__ float    g_alpha[N_EDGES * HEADS];        // logits, then exp
__device__ unsigned g_amax[N_NODES * HEADS];         // encoded float max
__device__ float    g_denom[N_NODES * HEADS];
__device__ double   g_red[4];                        // [sum1,sq1,sum2,sq2]

// ---------------- helpers ----------------------------------------------------
__device__ __forceinline__ unsigned fenc(float f) {
    unsigned u = __float_as_uint(f);
    return (u & 0x80000000u) ? ~u : (u | 0x80000000u);
}
__device__ __forceinline__ float fdec(unsigned u) {
    u = (u & 0x80000000u) ? (u & 0x7fffffffu) : ~u;
    return __uint_as_float(u);
}
__device__ __forceinline__ void red_add_v4(float* addr, float4 v) {
    asm volatile("red.global.add.v4.f32 [%0], {%1,%2,%3,%4};"
                 :: "l"(addr), "f"(v.x), "f"(v.y), "f"(v.z), "f"(v.w) : "memory");
}

// ---------------- generic SGEMM: C = A(MxK) @ B(KxN) + bias, optional relu ---
// All of M,N,K are multiples of the tile dims for every call site (checked).
#define BM 128
#define BN 128
#define BK 8
#define TM 8
#define TN 8

__global__ __launch_bounds__(256) void sgemm(
    const float* __restrict__ A, const float* __restrict__ B,
    const float* __restrict__ bias, float* __restrict__ C,
    int M, int N, int K, int relu)
{
    __shared__ float As[BK][BM];
    __shared__ float Bs[BK][BN];
    int tid = threadIdx.x;
    int bx = blockIdx.x, by = blockIdx.y;

    int arow = tid >> 1;            // 0..127
    int acol = (tid & 1) * 4;       // 0 or 4
    int brow = tid >> 5;            // 0..7
    int bcol = (tid & 31) * 4;      // 0..124
    int tx = tid & 15, ty = tid >> 4;

    const float* Ab = A + (size_t)(by * BM) * K;
    const float* Bb = B + bx * BN;

    float acc[TM][TN];
#pragma unroll
    for (int i = 0; i < TM; i++)
#pragma unroll
        for (int j = 0; j < TN; j++) acc[i][j] = 0.f;

    for (int k0 = 0; k0 < K; k0 += BK) {
        float4 av = *(const float4*)(Ab + (size_t)arow * K + k0 + acol);
        As[acol + 0][arow] = av.x;
        As[acol + 1][arow] = av.y;
        As[acol + 2][arow] = av.z;
        As[acol + 3][arow] = av.w;
        float4 bv = *(const float4*)(Bb + (size_t)(k0 + brow) * N + bcol);
        *(float4*)&Bs[brow][bcol] = bv;
        __syncthreads();
#pragma unroll
        for (int kk = 0; kk < BK; kk++) {
            float ar[TM], br[TN];
#pragma unroll
            for (int i = 0; i < TM; i++) ar[i] = As[kk][ty * TM + i];
#pragma unroll
            for (int j = 0; j < TN; j++) br[j] = Bs[kk][tx * TN + j];
#pragma unroll
            for (int i = 0; i < TM; i++)
#pragma unroll
                for (int j = 0; j < TN; j++) acc[i][j] = fmaf(ar[i], br[j], acc[i][j]);
        }
        __syncthreads();
    }

#pragma unroll
    for (int i = 0; i < TM; i++) {
        int row = by * BM + ty * TM + i;
#pragma unroll
        for (int j = 0; j < TN; j += 4) {
            int col = bx * BN + tx * TN + j;
            float4 v;
            v.x = acc[i][j + 0]; v.y = acc[i][j + 1];
            v.z = acc[i][j + 2]; v.w = acc[i][j + 3];
            if (bias) {
                v.x += bias[col + 0]; v.y += bias[col + 1];
                v.z += bias[col + 2]; v.w += bias[col + 3];
            }
            if (relu) {
                v.x = fmaxf(v.x, 0.f); v.y = fmaxf(v.y, 0.f);
                v.z = fmaxf(v.z, 0.f); v.w = fmaxf(v.w, 0.f);
            }
            *(float4*)(C + (size_t)row * N + col) = v;
        }
    }
}

// ---------------- per-block init: zero softmax state + LN accumulators -------
__global__ void init_kernel() {
    int i = blockIdx.x * blockDim.x + threadIdx.x;
    if (i < N_NODES * HEADS) { g_amax[i] = 0u; g_denom[i] = 0.f; }
    if (i < 4) g_red[i] = 0.0;
}

// ---------------- attention pass 1: logits + segment max ---------------------
// one warp per edge; lane covers 8 consecutive channels (head = lane/4)
__global__ __launch_bounds__(256) void edge_alpha(
    const int* __restrict__ ei, const float* __restrict__ xdist)
{
    int w = (blockIdx.x * blockDim.x + threadIdx.x) >> 5;
    int lane = threadIdx.x & 31;
    if (w >= N_EDGES) return;
    int src = ei[w], dst = ei[N_EDGES + w];

    const float4* qr = (const float4*)(g_q + (size_t)dst * DIM) + lane * 2;
    const float4* kr = (const float4*)(g_k + (size_t)src * DIM) + lane * 2;
    const float4* er = (const float4*)(g_e + (size_t)w * DIM) + lane * 2;

    float p = 0.f;
#pragma unroll
    for (int t = 0; t < 2; t++) {
        float4 qv = qr[t], kv = kr[t], ev = er[t];
        p = fmaf(qv.x, kv.x + ev.x, p);
        p = fmaf(qv.y, kv.y + ev.y, p);
        p = fmaf(qv.z, kv.z + ev.z, p);
        p = fmaf(qv.w, kv.w + ev.w, p);
    }
    p += __shfl_xor_sync(0xffffffffu, p, 1);
    p += __shfl_xor_sync(0xffffffffu, p, 2);
    if ((lane & 3) == 0) {
        int h = lane >> 2;
        float a = p * (1.0f / xdist[w]) * RSQRT_DH;
        g_alpha[(size_t)w * HEADS + h] = a;
        atomicMax(&g_amax[dst * HEADS + h], fenc(a));
    }
}

// ---------------- attention pass 2: exp + segment sum ------------------------
__global__ __launch_bounds__(256) void edge_exp(const int* __restrict__ ei)
{
    int i = blockIdx.x * blockDim.x + threadIdx.x;
    if (i >= N_EDGES * HEADS) return;
    int eidx = i >> 3, h = i & 7;
    int dst = ei[N_EDGES + eidx];
    float m = fdec(g_amax[dst * HEADS + h]);
    float ex = __expf(g_alpha[i] - m);
    g_alpha[i] = ex;
    atomicAdd(&g_denom[dst * HEADS + h], ex);
}

// ---------------- attention pass 3: weighted message scatter ------------------
__global__ __launch_bounds__(256) void edge_msg(const int* __restrict__ ei)
{
    int w = (blockIdx.x * blockDim.x + threadIdx.x) >> 5;
    int lane = threadIdx.x & 31;
    if (w >= N_EDGES) return;
    int src = ei[w], dst = ei[N_EDGES + w];
    int h = lane >> 2;
    float attn = g_alpha[(size_t)w * HEADS + h] / (g_denom[dst * HEADS + h] + 1e-16f);

    const float4* vr = (const float4*)(g_v + (size_t)src * DIM) + lane * 2;
    const float4* er = (const float4*)(g_e + (size_t)w * DIM) + lane * 2;
    float* op = g_out + (size_t)dst * DIM + lane * 8;

    float4 v0 = vr[0], v1 = vr[1], e0 = er[0], e1 = er[1];
    float4 r0 = make_float4((v0.x + e0.x) * attn, (v0.y + e0.y) * attn,
                            (v0.z + e0.z) * attn, (v0.w + e0.w) * attn);
    float4 r1 = make_float4((v1.x + e1.x) * attn, (v1.y + e1.y) * attn,
                            (v1.z + e1.z) * attn, (v1.w + e1.w) * attn);
    red_add_v4(op, r0);
    red_add_v4(op + 4, r1);
}

// ---------------- residual add + double-precision sum/sumsq reduction --------
__global__ __launch_bounds__(256) void resred(
    const float* __restrict__ a, const float* __restrict__ b,
    float* __restrict__ y, double* __restrict__ red)
{
    int i = blockIdx.x * blockDim.x + threadIdx.x;   // one float4 per thread
    float4 av = ((const float4*)a)[i];
    float4 bv = ((const float4*)b)[i];
    float4 s = make_float4(av.x + bv.x, av.y + bv.y, av.z + bv.z, av.w + bv.w);
    ((float4*)y)[i] = s;

    double ls = (double)s.x + (double)s.y + (double)s.z + (double)s.w;
    double lq = (double)s.x * s.x + (double)s.y * s.y +
                (double)s.z * s.z + (double)s.w * s.w;
#pragma unroll
    for (int o = 16; o > 0; o >>= 1) {
        ls += __shfl_down_sync(0xffffffffu, ls, o);
        lq += __shfl_down_sync(0xffffffffu, lq, o);
    }
    __shared__ double shs[8], shq[8];
    int wid = threadIdx.x >> 5, lane = threadIdx.x & 31;
    if (lane == 0) { shs[wid] = ls; shq[wid] = lq; }
    __syncthreads();
    if (threadIdx.x == 0) {
        double ts = 0, tq = 0;
#pragma unroll
        for (int k = 0; k < 8; k++) { ts += shs[k]; tq += shq[k]; }
        atomicAdd(&red[0], ts);
        atomicAdd(&red[1], tq);
    }
}

// ---------------- graph layernorm apply --------------------------------------
__global__ __launch_bounds__(256) void lnapply(
    const float* __restrict__ y, const float* __restrict__ g,
    const float* __restrict__ b, float* __restrict__ o,
    const double* __restrict__ red)
{
    int i = blockIdx.x * blockDim.x + threadIdx.x;   // one float4 per thread
    double mean = red[0] / (double)LN_CNT;
    double var  = red[1] / (double)LN_CNT - mean * mean;
    if (var < 0) var = 0;
    float inv = 1.0f / ((float)sqrt(var) + LN_EPS);
    float mu = (float)mean;

    int c = (i * 4) % DIM;
    float4 yv = ((const float4*)y)[i];
    float4 gv = *(const float4*)(g + c);
    float4 bv = *(const float4*)(b + c);
    float4 r;
    r.x = (yv.x - mu) * inv * gv.x + bv.x;
    r.y = (yv.y - mu) * inv * gv.y + bv.y;
    r.z = (yv.z - mu) * inv * gv.z + bv.z;
    r.w = (yv.w - mu) * inv * gv.w + bv.w;
    ((float4*)o)[i] = r;
}

// ---------------- host orchestration -----------------------------------------
extern "C" void kernel_launch(void* const* d_in, const int* in_sizes, int n_in,
                              void* d_out, int out_size)
{
    const float* x_in   = (const float*)d_in[0];
    const int*   ei     = (const int*)d_in[1];
    const float* x_edge = (const float*)d_in[2];
    const float* x_dist = (const float*)d_in[3];
    const float* Wq_a   = (const float*)d_in[4];
    const float* bq_a   = (const float*)d_in[5];
    const float* Wk_a   = (const float*)d_in[6];
    const float* bk_a   = (const float*)d_in[7];
    const float* Wv_a   = (const float*)d_in[8];
    const float* bv_a   = (const float*)d_in[9];
    const float* We_a   = (const float*)d_in[10];
    const float* Ws_a   = (const float*)d_in[11];
    const float* bs_a   = (const float*)d_in[12];
    const float* g1_a   = (const float*)d_in[13];
    const float* b1_a   = (const float*)d_in[14];
    const float* W1_a   = (const float*)d_in[15];
    const float* c1_a   = (const float*)d_in[16];
    const float* W2_a   = (const float*)d_in[17];
    const float* c2_a   = (const float*)d_in[18];
    const float* g2_a   = (const float*)d_in[19];
    const float* b2_a   = (const float*)d_in[20];

    float *e_, *q_, *k_, *v_, *out_, *y_, *x_, *h_;
    double* red_;
    cudaGetSymbolAddress((void**)&e_,   g_e);
    cudaGetSymbolAddress((void**)&q_,   g_q);
    cudaGetSymbolAddress((void**)&k_,   g_k);
    cudaGetSymbolAddress((void**)&v_,   g_v);
    cudaGetSymbolAddress((void**)&out_, g_out);
    cudaGetSymbolAddress((void**)&y_,   g_y);
    cudaGetSymbolAddress((void**)&x_,   g_x);
    cudaGetSymbolAddress((void**)&h_,   g_h);
    cudaGetSymbolAddress((void**)&red_, g_red);

    const float* xcur = x_in;
    const int elem4 = LN_CNT / 4;                // 1,024,000 float4
    const dim3 gN(DIM / BN, N_NODES / BM);       // (2, 125)
    const dim3 gE(DIM / BN, N_EDGES / BM);       // (2, 2000)
    const dim3 gF1(HID / BN, N_NODES / BM);      // (8, 125)

    for (int blk = 0; blk < 3; blk++) {
        const float* Wq = Wq_a + (size_t)blk * DIM * DIM;
        const float* Wk = Wk_a + (size_t)blk * DIM * DIM;
        const float* Wv = Wv_a + (size_t)blk * DIM * DIM;
        const float* We = We_a + (size_t)blk * DIM * DIM;
        const float* Ws = Ws_a + (size_t)blk * DIM * DIM;
        const float* W1 = W1_a + (size_t)blk * DIM * HID;
        const float* W2 = W2_a + (size_t)blk * HID * DIM;
        const float* bq = bq_a + blk * DIM;
        const float* bk = bk_a + blk * DIM;
        const float* bv = bv_a + blk * DIM;
        const float* bs = bs_a + blk * DIM;
        const float* g1 = g1_a + blk * DIM;
        const float* b1 = b1_a + blk * DIM;
        const float* c1 = c1_a + blk * HID;
        const float* c2 = c2_a + blk * DIM;
        const float* g2 = g2_a + blk * DIM;
        const float* b2 = b2_a + blk * DIM;

        // node + edge projections (skip term goes straight into the msg accumulator)
        sgemm<<<gN, 256>>>(xcur, Wq, bq, q_,  N_NODES, DIM, DIM, 0);
        sgemm<<<gN, 256>>>(xcur, Wk, bk, k_,  N_NODES, DIM, DIM, 0);
        sgemm<<<gN, 256>>>(xcur, Wv, bv, v_,  N_NODES, DIM, DIM, 0);
        sgemm<<<gN, 256>>>(xcur, Ws, bs, out_, N_NODES, DIM, DIM, 0);
        sgemm<<<gE, 256>>>(x_edge, We, nullptr, e_, N_EDGES, DIM, DIM, 0);

        init_kernel<<<(N_NODES * HEADS + 255) / 256, 256>>>();

        edge_alpha<<<N_EDGES / 8, 256>>>(ei, x_dist);
        edge_exp<<<N_EDGES * HEADS / 256, 256>>>(ei);
        edge_msg<<<N_EDGES / 8, 256>>>(ei);

        // residual + graph LN 1
        resred<<<elem4 / 256, 256>>>(xcur, out_, y_, red_ + 0);
        lnapply<<<elem4 / 256, 256>>>(y_, g1, b1, y_, red_ + 0);

        // FFN
        sgemm<<<gF1, 256>>>(y_, W1, c1, h_,  N_NODES, HID, DIM, 1);
        sgemm<<<gN, 256>>>(h_, W2, c2, out_, N_NODES, DIM, HID, 0);

        // residual + graph LN 2
        resred<<<elem4 / 256, 256>>>(y_, out_, out_, red_ + 2);
        float* xdst = (blk == 2) ? (float*)d_out : x_;
        lnapply<<<elem4 / 256, 256>>>(out_, g2, b2, xdst, red_ + 2);

        xcur = x_;
    }
}

// round 5
// speedup vs baseline: 1.8804x; 1.8804x over previous
#include <cuda_runtime.h>
#include <cuda_fp16.h>
#include <math.h>
#include <stdint.h>

#define N_NODES 16000
#define N_EDGES 256000
#define DIM 256
#define HEADS 8
#define HID 1024
#define LN_CNT (N_NODES * DIM)
#define LN_EPS 1e-5f
#define RSQRT_DH 0.17677669529663687f

// cat-weight table offsets (halves, per transformer block). each matrix is [N, 3K]
#define OW_Q 0
#define OW_K 196608
#define OW_V 393216
#define OW_E 589824
#define OW_S 786432
#define OW_1 983040
#define OW_2 1769472
#define WB   2555904

// ---------------- scratch (static device globals; no allocation) -------------
__device__ float    g_e[(size_t)N_EDGES * DIM];      // 262 MB edge projection
__device__ float    g_q[N_NODES * DIM];
__device__ float    g_k[N_NODES * DIM];
__device__ float    g_v[N_NODES * DIM];
__device__ float    g_out[N_NODES * DIM];
__device__ float    g_y[N_NODES * DIM];
__device__ float    g_x[N_NODES * DIM];
__device__ float    g_h[(size_t)N_NODES * HID];
__device__ float    g_alpha[N_EDGES * HEADS];
__device__ unsigned g_amax[N_NODES * HEADS];
__device__ float    g_denom[N_NODES * HEADS];
__device__ double   g_red[4];
// K-concatenated fp16 operands: activations [hi|lo|hi], weights [hi|hi|lo]
__device__ __half   g_xe_cat[(size_t)N_EDGES * 3 * DIM];   // 393 MB
__device__ __half   g_x_cat[(size_t)N_NODES * 3 * DIM];
__device__ __half   g_y_cat[(size_t)N_NODES * 3 * DIM];
__device__ __half   g_h_cat[(size_t)N_NODES * 3 * HID];    // 98 MB
__device__ __half   g_wt_cat[3 * WB];

// ---------------- helpers -----------------------------------------------------
__device__ __forceinline__ uint32_t smem_u32(const void* p) {
    uint32_t a;
    asm("{ .reg .u64 t; cvta.to.shared.u64 t, %1; cvt.u32.u64 %0, t; }"
        : "=r"(a) : "l"(p));
    return a;
}
__device__ __forceinline__ unsigned fenc(float f) {
    unsigned u = __float_as_uint(f);
    return (u & 0x80000000u) ? ~u : (u | 0x80000000u);
}
__device__ __forceinline__ float fdec(unsigned u) {
    u = (u & 0x80000000u) ? (u & 0x7fffffffu) : ~u;
    return __uint_as_float(u);
}
__device__ __forceinline__ void red_add_v4(float* addr, float4 v) {
    asm volatile("red.global.add.v4.f32 [%0], {%1,%2,%3,%4};"
                 :: "l"(addr), "f"(v.x), "f"(v.y), "f"(v.z), "f"(v.w) : "memory");
}
__device__ __forceinline__ uint32_t pack_h2(__half a, __half b) {
    __half2 h2 = __halves2half2(a, b);
    return *(uint32_t*)&h2;
}

// ---------------- tensor-core GEMM via mma.sync (fp16 in, fp32 out) -----------
// C[M,N] = A[M,K3] @ B[N,K3]^T  (+bias, optional relu)
// Tiles: CTA 128x128, chunk K=64 halves, 8 warps (2m x 4n), warp tile 64x32.
#define GEMM_SMEM 65536

__device__ __forceinline__ void cp16(uint32_t dst, const void* src) {
    asm volatile("cp.async.cg.shared.global [%0], [%1], 16;"
                 :: "r"(dst), "l"(src) : "memory");
}
__device__ __forceinline__ void ldsm_x4(uint32_t* r, uint32_t addr) {
    asm volatile("ldmatrix.sync.aligned.m8n8.x4.shared.b16 {%0,%1,%2,%3}, [%4];"
                 : "=r"(r[0]), "=r"(r[1]), "=r"(r[2]), "=r"(r[3]) : "r"(addr));
}
__device__ __forceinline__ void ldsm_x2(uint32_t* r, uint32_t addr) {
    asm volatile("ldmatrix.sync.aligned.m8n8.x2.shared.b16 {%0,%1}, [%2];"
                 : "=r"(r[0]), "=r"(r[1]) : "r"(addr));
}
__device__ __forceinline__ void mma16816(float* c, const uint32_t* a, const uint32_t* b) {
    asm volatile(
        "mma.sync.aligned.m16n8k16.row.col.f32.f16.f16.f32 "
        "{%0,%1,%2,%3}, {%4,%5,%6,%7}, {%8,%9}, {%0,%1,%2,%3};"
        : "+f"(c[0]), "+f"(c[1]), "+f"(c[2]), "+f"(c[3])
        : "r"(a[0]), "r"(a[1]), "r"(a[2]), "r"(a[3]), "r"(b[0]), "r"(b[1]));
}

__device__ __forceinline__ void load_chunk(
    uint32_t smA, uint32_t smB,
    const __half* __restrict__ A, const __half* __restrict__ B,
    size_t rowA0, size_t rowB0, int K3, int k0, int tid)
{
#pragma unroll
    for (int i = 0; i < 4; i++) {
        int u = tid + (i << 8);
        int row = u >> 3, kk = u & 7;
        uint32_t off = (uint32_t)(row * 128 + kk * 16);
        uint32_t sw = off ^ ((off >> 3) & 0x70);
        cp16(smA + sw, A + (rowA0 + row) * (size_t)K3 + k0 + kk * 8);
        cp16(smB + sw, B + (rowB0 + row) * (size_t)K3 + k0 + kk * 8);
    }
}

__global__ __launch_bounds__(256) void gemm_mma(
    const __half* __restrict__ A, const __half* __restrict__ B,
    const float* __restrict__ bias, float* __restrict__ C,
    int M, int N, int K3, int relu)
{
    extern __shared__ __align__(128) char smem[];
    uint32_t sbase = smem_u32(smem);

    int tid = threadIdx.x, lane = tid & 31, wid = tid >> 5;
    int warpM = wid >> 2, warpN = wid & 3;
    int tN = blockIdx.x, tM = blockIdx.y;
    size_t rowA0 = (size_t)tM * 128;
    size_t rowB0 = (size_t)tN * 128;
    int nch = K3 >> 6;

    float acc[4][4][4];
#pragma unroll
    for (int i = 0; i < 4; i++)
#pragma unroll
        for (int j = 0; j < 4; j++)
#pragma unroll
            for (int t = 0; t < 4; t++) acc[i][j][t] = 0.f;

    // prefetch chunk 0 into buffer 0
    load_chunk(sbase, sbase + 16384, A, B, rowA0, rowB0, K3, 0, tid);
    asm volatile("cp.async.commit_group;" ::: "memory");

    for (int c = 0; c < nch; c++) {
        if (c + 1 < nch) {
            uint32_t nb = ((c + 1) & 1) ? 32768u : 0u;
            load_chunk(sbase + nb, sbase + nb + 16384, A, B, rowA0, rowB0,
                       K3, (c + 1) << 6, tid);
            asm volatile("cp.async.commit_group;" ::: "memory");
            asm volatile("cp.async.wait_group 1;" ::: "memory");
        } else {
            asm volatile("cp.async.wait_group 0;" ::: "memory");
        }
        __syncthreads();

        uint32_t aB = sbase + ((c & 1) ? 32768u : 0u);
        uint32_t bB = aB + 16384;
#pragma unroll
        for (int ks = 0; ks < 4; ks++) {
            uint32_t af[4][4], bf[4][2];
#pragma unroll
            for (int mf = 0; mf < 4; mf++) {
                int row = warpM * 64 + mf * 16 + (lane & 15);
                uint32_t off = (uint32_t)(row * 128 + ks * 32 + ((lane >> 4) << 4));
                off ^= (off >> 3) & 0x70;
                ldsm_x4(af[mf], aB + off);
            }
#pragma unroll
            for (int nf = 0; nf < 4; nf++) {
                int row = warpN * 32 + nf * 8 + (lane & 7);
                uint32_t off = (uint32_t)(row * 128 + ks * 32 + (((lane >> 3) & 1) << 4));
                off ^= (off >> 3) & 0x70;
                ldsm_x2(bf[nf], bB + off);
            }
#pragma unroll
            for (int mf = 0; mf < 4; mf++)
#pragma unroll
                for (int nf = 0; nf < 4; nf++)
                    mma16816(acc[mf][nf], af[mf], bf[nf]);
        }
        __syncthreads();
    }

    // epilogue: direct stores (float2 per frag-row)
    int m0 = tM * 128 + warpM * 64;
    int n0 = tN * 128 + warpN * 32;
#pragma unroll
    for (int mf = 0; mf < 4; mf++) {
#pragma unroll
        for (int nf = 0; nf < 4; nf++) {
            int r = m0 + mf * 16 + (lane >> 2);
            int col = n0 + nf * 8 + ((lane & 3) << 1);
            float b0 = bias ? __ldg(bias + col) : 0.f;
            float b1 = bias ? __ldg(bias + col + 1) : 0.f;
            float v00 = acc[mf][nf][0] + b0, v01 = acc[mf][nf][1] + b1;
            float v10 = acc[mf][nf][2] + b0, v11 = acc[mf][nf][3] + b1;
            if (relu) {
                v00 = fmaxf(v00, 0.f); v01 = fmaxf(v01, 0.f);
                v10 = fmaxf(v10, 0.f); v11 = fmaxf(v11, 0.f);
            }
            *(float2*)(C + (size_t)r * N + col) = make_float2(v00, v01);
            *(float2*)(C + (size_t)(r + 8) * N + col) = make_float2(v10, v11);
        }
    }
}

// ---------------- fp32 -> K-concatenated fp16 [hi|lo|hi] ----------------------
__global__ __launch_bounds__(256) void cvt_cat(
    const float* __restrict__ s, __half* __restrict__ d, int K, int n4)
{
    int i = blockIdx.x * blockDim.x + threadIdx.x;
    if (i >= n4) return;
    int i4 = i * 4;
    int row = i4 / K, col = i4 % K;
    float4 v = ((const float4*)s)[i];
    float vv[4] = {v.x, v.y, v.z, v.w};
    __half h[4], l[4];
#pragma unroll
    for (int j = 0; j < 4; j++) {
        h[j] = __float2half_rn(vv[j]);
        l[j] = __float2half_rn(vv[j] - __half2float(h[j]));
    }
    size_t base = (size_t)row * 3 * K + col;
    uint2 uh = make_uint2(pack_h2(h[0], h[1]), pack_h2(h[2], h[3]));
    uint2 ul = make_uint2(pack_h2(l[0], l[1]), pack_h2(l[2], l[3]));
    *(uint2*)(d + base) = uh;
    *(uint2*)(d + base + K) = ul;
    *(uint2*)(d + base + 2 * K) = uh;
}

// ---------------- weight transpose + cat convert [hi|hi|lo] -------------------
// W [K,N] row-major -> Wcat [N, 3K]
__global__ void tconv(const float* __restrict__ W, __half* __restrict__ out,
                      int K, int N)
{
    __shared__ float t[32][33];
    int tx = threadIdx.x, ty = threadIdx.y;       // 32 x 8
    int n0 = blockIdx.x * 32, k0 = blockIdx.y * 32;
#pragma unroll
    for (int r = 0; r < 4; r++)
        t[ty + 8 * r][tx] = W[(size_t)(k0 + ty + 8 * r) * N + n0 + tx];
    __syncthreads();
#pragma unroll
    for (int r = 0; r < 4; r++) {
        int nl = ty + 8 * r;
        float v = t[tx][nl];
        size_t o = (size_t)(n0 + nl) * 3 * K + k0 + tx;
        __half h = __float2half_rn(v);
        __half l = __float2half_rn(v - __half2float(h));
        out[o] = h;
        out[o + K] = h;
        out[o + 2 * K] = l;
    }
}

// ---------------- per-block init ----------------------------------------------
__global__ void init_kernel() {
    int i = blockIdx.x * blockDim.x + threadIdx.x;
    if (i < N_NODES * HEADS) { g_amax[i] = 0u; g_denom[i] = 0.f; }
    if (i < 4) g_red[i] = 0.0;
}

// ---------------- attention pass 1: logits + segment max ----------------------
__global__ __launch_bounds__(256) void edge_alpha(
    const int* __restrict__ ei, const float* __restrict__ xdist)
{
    int w = (blockIdx.x * blockDim.x + threadIdx.x) >> 5;
    int lane = threadIdx.x & 31;
    if (w >= N_EDGES) return;
    int src = ei[w], dst = ei[N_EDGES + w];

    const float4* qr = (const float4*)(g_q + (size_t)dst * DIM) + lane * 2;
    const float4* kr = (const float4*)(g_k + (size_t)src * DIM) + lane * 2;
    const float4* er = (const float4*)(g_e + (size_t)w * DIM) + lane * 2;

    float p = 0.f;
#pragma unroll
    for (int t = 0; t < 2; t++) {
        float4 qv = qr[t], kv = kr[t], ev = er[t];
        p = fmaf(qv.x, kv.x + ev.x, p);
        p = fmaf(qv.y, kv.y + ev.y, p);
        p = fmaf(qv.z, kv.z + ev.z, p);
        p = fmaf(qv.w, kv.w + ev.w, p);
    }
    p += __shfl_xor_sync(0xffffffffu, p, 1);
    p += __shfl_xor_sync(0xffffffffu, p, 2);
    if ((lane & 3) == 0) {
        int h = lane >> 2;
        float a = p * (1.0f / xdist[w]) * RSQRT_DH;
        g_alpha[(size_t)w * HEADS + h] = a;
        atomicMax(&g_amax[dst * HEADS + h], fenc(a));
    }
}

// ---------------- attention pass 2: exp + segment sum -------------------------
__global__ __launch_bounds__(256) void edge_exp(const int* __restrict__ ei)
{
    int i = blockIdx.x * blockDim.x + threadIdx.x;
    if (i >= N_EDGES * HEADS) return;
    int eidx = i >> 3, h = i & 7;
    int dst = ei[N_EDGES + eidx];
    float m = fdec(g_amax[dst * HEADS + h]);
    float ex = __expf(g_alpha[i] - m);
    g_alpha[i] = ex;
    atomicAdd(&g_denom[dst * HEADS + h], ex);
}

// ---------------- attention pass 3: weighted message scatter ------------------
__global__ __launch_bounds__(256) void edge_msg(const int* __restrict__ ei)
{
    int w = (blockIdx.x * blockDim.x + threadIdx.x) >> 5;
    int lane = threadIdx.x & 31;
    if (w >= N_EDGES) return;
    int src = ei[w], dst = ei[N_EDGES + w];
    int h = lane >> 2;
    float attn = g_alpha[(size_t)w * HEADS + h] / (g_denom[dst * HEADS + h] + 1e-16f);

    const float4* vr = (const float4*)(g_v + (size_t)src * DIM) + lane * 2;
    const float4* er = (const float4*)(g_e + (size_t)w * DIM) + lane * 2;
    float* op = g_out + (size_t)dst * DIM + lane * 8;

    float4 v0 = vr[0], v1 = vr[1], e0 = er[0], e1 = er[1];
    float4 r0 = make_float4((v0.x + e0.x) * attn, (v0.y + e0.y) * attn,
                            (v0.z + e0.z) * attn, (v0.w + e0.w) * attn);
    float4 r1 = make_float4((v1.x + e1.x) * attn, (v1.y + e1.y) * attn,
                            (v1.z + e1.z) * attn, (v1.w + e1.w) * attn);
    red_add_v4(op, r0);
    red_add_v4(op + 4, r1);
}

// ---------------- residual add + double-precision sum/sumsq reduction ---------
__global__ __launch_bounds__(256) void resred(
    const float* __restrict__ a, const float* __restrict__ b,
    float* __restrict__ y, double* __restrict__ red)
{
    int i = blockIdx.x * blockDim.x + threadIdx.x;
    float4 av = ((const float4*)a)[i];
    float4 bv = ((const float4*)b)[i];
    float4 s = make_float4(av.x + bv.x, av.y + bv.y, av.z + bv.z, av.w + bv.w);
    ((float4*)y)[i] = s;

    double ls = (double)s.x + (double)s.y + (double)s.z + (double)s.w;
    double lq = (double)s.x * s.x + (double)s.y * s.y +
                (double)s.z * s.z + (double)s.w * s.w;
#pragma unroll
    for (int o = 16; o > 0; o >>= 1) {
        ls += __shfl_down_sync(0xffffffffu, ls, o);
        lq += __shfl_down_sync(0xffffffffu, lq, o);
    }
    __shared__ double shs[8], shq[8];
    int wid = threadIdx.x >> 5, lane = threadIdx.x & 31;
    if (lane == 0) { shs[wid] = ls; shq[wid] = lq; }
    __syncthreads();
    if (threadIdx.x == 0) {
        double ts = 0, tq = 0;
#pragma unroll
        for (int k = 0; k < 8; k++) { ts += shs[k]; tq += shq[k]; }
        atomicAdd(&red[0], ts);
        atomicAdd(&red[1], tq);
    }
}

// ---------------- graph layernorm apply + cat fp16 emit ------------------------
__global__ __launch_bounds__(256) void lnapply(
    const float* __restrict__ y, const float* __restrict__ g,
    const float* __restrict__ b, float* __restrict__ o,
    __half* __restrict__ ocat, const double* __restrict__ red)
{
    int i = blockIdx.x * blockDim.x + threadIdx.x;
    double mean = red[0] / (double)LN_CNT;
    double var  = red[1] / (double)LN_CNT - mean * mean;
    if (var < 0) var = 0;
    float inv = 1.0f / ((float)sqrt(var) + LN_EPS);
    float mu = (float)mean;

    int i4 = i * 4;
    int c = i4 % DIM;
    int row = i4 / DIM;
    float4 yv = ((const float4*)y)[i];
    float4 gv = *(const float4*)(g + c);
    float4 bv = *(const float4*)(b + c);
    float4 r;
    r.x = (yv.x - mu) * inv * gv.x + bv.x;
    r.y = (yv.y - mu) * inv * gv.y + bv.y;
    r.z = (yv.z - mu) * inv * gv.z + bv.z;
    r.w = (yv.w - mu) * inv * gv.w + bv.w;
    ((float4*)o)[i] = r;

    float vv[4] = {r.x, r.y, r.z, r.w};
    __half h[4], l[4];
#pragma unroll
    for (int j = 0; j < 4; j++) {
        h[j] = __float2half_rn(vv[j]);
        l[j] = __float2half_rn(vv[j] - __half2float(h[j]));
    }
    size_t base = (size_t)row * 3 * DIM + c;
    uint2 uh = make_uint2(pack_h2(h[0], h[1]), pack_h2(h[2], h[3]));
    uint2 ul = make_uint2(pack_h2(l[0], l[1]), pack_h2(l[2], l[3]));
    *(uint2*)(ocat + base) = uh;
    *(uint2*)(ocat + base + DIM) = ul;
    *(uint2*)(ocat + base + 2 * DIM) = uh;
}

// ---------------- host orchestration ------------------------------------------
extern "C" void kernel_launch(void* const* d_in, const int* in_sizes, int n_in,
                              void* d_out, int out_size)
{
    const float* x_in   = (const float*)d_in[0];
    const int*   ei     = (const int*)d_in[1];
    const float* x_edge = (const float*)d_in[2];
    const float* x_dist = (const float*)d_in[3];
    const float* Wq_a   = (const float*)d_in[4];
    const float* bq_a   = (const float*)d_in[5];
    const float* Wk_a   = (const float*)d_in[6];
    const float* bk_a   = (const float*)d_in[7];
    const float* Wv_a   = (const float*)d_in[8];
    const float* bv_a   = (const float*)d_in[9];
    const float* We_a   = (const float*)d_in[10];
    const float* Ws_a   = (const float*)d_in[11];
    const float* bs_a   = (const float*)d_in[12];
    const float* g1_a   = (const float*)d_in[13];
    const float* b1_a   = (const float*)d_in[14];
    const float* W1_a   = (const float*)d_in[15];
    const float* c1_a   = (const float*)d_in[16];
    const float* W2_a   = (const float*)d_in[17];
    const float* c2_a   = (const float*)d_in[18];
    const float* g2_a   = (const float*)d_in[19];
    const float* b2_a   = (const float*)d_in[20];

    static int smem_set = 0;
    if (!smem_set) {
        cudaFuncSetAttribute(gemm_mma, cudaFuncAttributeMaxDynamicSharedMemorySize,
                             GEMM_SMEM);
        smem_set = 1;
    }

    float *e_, *q_, *k_, *v_, *out_, *y_, *x_, *h_;
    double* red_;
    __half *xec_, *xc_, *yc_, *hc_, *wt_;
    cudaGetSymbolAddress((void**)&e_,   g_e);
    cudaGetSymbolAddress((void**)&q_,   g_q);
    cudaGetSymbolAddress((void**)&k_,   g_k);
    cudaGetSymbolAddress((void**)&v_,   g_v);
    cudaGetSymbolAddress((void**)&out_, g_out);
    cudaGetSymbolAddress((void**)&y_,   g_y);
    cudaGetSymbolAddress((void**)&x_,   g_x);
    cudaGetSymbolAddress((void**)&h_,   g_h);
    cudaGetSymbolAddress((void**)&red_, g_red);
    cudaGetSymbolAddress((void**)&xec_, g_xe_cat);
    cudaGetSymbolAddress((void**)&xc_,  g_x_cat);
    cudaGetSymbolAddress((void**)&yc_,  g_y_cat);
    cudaGetSymbolAddress((void**)&hc_,  g_h_cat);
    cudaGetSymbolAddress((void**)&wt_,  g_wt_cat);

    const int elem4 = LN_CNT / 4;

    // one-time conversions
    cvt_cat<<<(elem4 + 255) / 256, 256>>>(x_in, xc_, DIM, elem4);
    {
        int n4 = N_EDGES * DIM / 4;
        cvt_cat<<<(n4 + 255) / 256, 256>>>(x_edge, xec_, DIM, n4);
    }
    dim3 tb(32, 8);
    for (int b = 0; b < 3; b++) {
        size_t wb = (size_t)b * WB;
        tconv<<<dim3(8, 8),  tb>>>(Wq_a + (size_t)b * DIM * DIM, wt_ + wb + OW_Q, DIM, DIM);
        tconv<<<dim3(8, 8),  tb>>>(Wk_a + (size_t)b * DIM * DIM, wt_ + wb + OW_K, DIM, DIM);
        tconv<<<dim3(8, 8),  tb>>>(Wv_a + (size_t)b * DIM * DIM, wt_ + wb + OW_V, DIM, DIM);
        tconv<<<dim3(8, 8),  tb>>>(We_a + (size_t)b * DIM * DIM, wt_ + wb + OW_E, DIM, DIM);
        tconv<<<dim3(8, 8),  tb>>>(Ws_a + (size_t)b * DIM * DIM, wt_ + wb + OW_S, DIM, DIM);
        tconv<<<dim3(32, 8), tb>>>(W1_a + (size_t)b * DIM * HID, wt_ + wb + OW_1, DIM, HID);
        tconv<<<dim3(8, 32), tb>>>(W2_a + (size_t)b * HID * DIM, wt_ + wb + OW_2, HID, DIM);
    }

    const float* xcur = x_in;
    for (int blk = 0; blk < 3; blk++) {
        size_t wb = (size_t)blk * WB;
        const float* bq = bq_a + blk * DIM;
        const float* bk = bk_a + blk * DIM;
        const float* bv = bv_a + blk * DIM;
        const float* bs = bs_a + blk * DIM;
        const float* g1 = g1_a + blk * DIM;
        const float* b1 = b1_a + blk * DIM;
        const float* c1 = c1_a + blk * HID;
        const float* c2 = c2_a + blk * DIM;
        const float* g2 = g2_a + blk * DIM;
        const float* b2 = b2_a + blk * DIM;

        // node + edge projections (HMMA tensor cores, K'=768)
        gemm_mma<<<dim3(2, 125), 256, GEMM_SMEM>>>(xc_, wt_ + wb + OW_Q, bq, q_,
                                                   N_NODES, DIM, 3 * DIM, 0);
        gemm_mma<<<dim3(2, 125), 256, GEMM_SMEM>>>(xc_, wt_ + wb + OW_K, bk, k_,
                                                   N_NODES, DIM, 3 * DIM, 0);
        gemm_mma<<<dim3(2, 125), 256, GEMM_SMEM>>>(xc_, wt_ + wb + OW_V, bv, v_,
                                                   N_NODES, DIM, 3 * DIM, 0);
        gemm_mma<<<dim3(2, 125), 256, GEMM_SMEM>>>(xc_, wt_ + wb + OW_S, bs, out_,
                                                   N_NODES, DIM, 3 * DIM, 0);
        gemm_mma<<<dim3(2, 2000), 256, GEMM_SMEM>>>(xec_, wt_ + wb + OW_E, nullptr, e_,
                                                    N_EDGES, DIM, 3 * DIM, 0);

        init_kernel<<<(N_NODES * HEADS + 255) / 256, 256>>>();
        edge_alpha<<<N_EDGES / 8, 256>>>(ei, x_dist);
        edge_exp<<<N_EDGES * HEADS / 256, 256>>>(ei);
        edge_msg<<<N_EDGES / 8, 256>>>(ei);

        // residual + graph LN 1
        resred<<<elem4 / 256, 256>>>(xcur, out_, y_, red_ + 0);
        lnapply<<<elem4 / 256, 256>>>(y_, g1, b1, y_, yc_, red_ + 0);

        // FFN
        gemm_mma<<<dim3(8, 125), 256, GEMM_SMEM>>>(yc_, wt_ + wb + OW_1, c1, h_,
                                                   N_NODES, HID, 3 * DIM, 1);
        {
            int n4 = N_NODES * HID / 4;
            cvt_cat<<<(n4 + 255) / 256, 256>>>(h_, hc_, HID, n4);
        }
        gemm_mma<<<dim3(2, 125), 256, GEMM_SMEM>>>(hc_, wt_ + wb + OW_2, c2, out_,
                                                   N_NODES, DIM, 3 * HID, 0);

        // residual + graph LN 2
        resred<<<elem4 / 256, 256>>>(y_, out_, out_, red_ + 2);
        float* xdst = (blk == 2) ? (float*)d_out : x_;
        lnapply<<<elem4 / 256, 256>>>(out_, g2, b2, xdst, xc_, red_ + 2);

        xcur = x_;
    }
}

// round 6
// speedup vs baseline: 2.1463x; 1.1414x over previous
#include <cuda_runtime.h>
#include <cuda_fp16.h>
#include <math.h>
#include <stdint.h>

#define N_NODES 16000
#define N_EDGES 256000
#define DIM 256
#define HEADS 8
#define HID 1024
#define LN_CNT (N_NODES * DIM)
#define LN_EPS 1e-5f
#define RSQRT_DH 0.17677669529663687f

// cat-weight table offsets (halves, per transformer block)
#define OW_QKVS 0              // [1024, 768]  (Q|K|V|S rows)
#define OW_E    786432         // [256, 512]   2-cat
#define OW_1    917504         // [1024, 768]
#define OW_2    1703936        // [256, 3072]
#define WB      2490368

// ---------------- scratch (static device globals; no allocation) -------------
__device__ float    g_qkvs[(size_t)N_NODES * 1024];       // q|k|v|skip per node
__device__ __half   g_e_h[(size_t)N_EDGES * DIM];         // 131 MB edge projection
__device__ float    g_out[N_NODES * DIM];                 // msg accum / ffn2 out
__device__ float    g_y[N_NODES * DIM];
__device__ float    g_x[N_NODES * DIM];
__device__ float    g_alpha[N_EDGES * HEADS];
__device__ unsigned g_amax[N_NODES * HEADS];
__device__ float    g_denom[N_NODES * HEADS];
__device__ double   g_red[4];
__device__ float    g_bqkvs[3 * 1024];
__device__ __half   g_xe_cat2[(size_t)N_EDGES * 2 * DIM]; // [hi|lo] 262 MB
__device__ __half   g_x_cat[(size_t)N_NODES * 3 * DIM];   // [hi|lo|hi]
__device__ __half   g_y_cat[(size_t)N_NODES * 3 * DIM];
__device__ __half   g_h_cat[(size_t)N_NODES * 3 * HID];
__device__ __half   g_wt_cat[3 * WB];

// ---------------- helpers -----------------------------------------------------
__device__ __forceinline__ uint32_t smem_u32(const void* p) {
    uint32_t a;
    asm("{ .reg .u64 t; cvta.to.shared.u64 t, %1; cvt.u32.u64 %0, t; }"
        : "=r"(a) : "l"(p));
    return a;
}
__device__ __forceinline__ unsigned fenc(float f) {
    unsigned u = __float_as_uint(f);
    return (u & 0x80000000u) ? ~u : (u | 0x80000000u);
}
__device__ __forceinline__ float fdec(unsigned u) {
    u = (u & 0x80000000u) ? (u & 0x7fffffffu) : ~u;
    return __uint_as_float(u);
}
__device__ __forceinline__ void red_add_v4(float* addr, float4 v) {
    asm volatile("red.global.add.v4.f32 [%0], {%1,%2,%3,%4};"
                 :: "l"(addr), "f"(v.x), "f"(v.y), "f"(v.z), "f"(v.w) : "memory");
}
__device__ __forceinline__ uint32_t pack_h2(__half a, __half b) {
    __half2 h2 = __halves2half2(a, b);
    return *(uint32_t*)&h2;
}

// ---------------- tensor-core GEMM via mma.sync (fp16 in, fp32 out) -----------
// C[M,N] = A[M,K3] @ B[N,K3]^T  (+bias, optional relu)
// CTA 128x128, K-chunk 64 halves, 3-stage cp.async, 8 warps (2m x 4n).
#define GEMM_SMEM 98304

__device__ __forceinline__ void cp16(uint32_t dst, const void* src) {
    asm volatile("cp.async.cg.shared.global [%0], [%1], 16;"
                 :: "r"(dst), "l"(src) : "memory");
}
__device__ __forceinline__ void ldsm_x4(uint32_t* r, uint32_t addr) {
    asm volatile("ldmatrix.sync.aligned.m8n8.x4.shared.b16 {%0,%1,%2,%3}, [%4];"
                 : "=r"(r[0]), "=r"(r[1]), "=r"(r[2]), "=r"(r[3]) : "r"(addr));
}
__device__ __forceinline__ void ldsm_x2(uint32_t* r, uint32_t addr) {
    asm volatile("ldmatrix.sync.aligned.m8n8.x2.shared.b16 {%0,%1}, [%2];"
                 : "=r"(r[0]), "=r"(r[1]) : "r"(addr));
}
__device__ __forceinline__ void mma16816(float* c, const uint32_t* a, const uint32_t* b) {
    asm volatile(
        "mma.sync.aligned.m16n8k16.row.col.f32.f16.f16.f32 "
        "{%0,%1,%2,%3}, {%4,%5,%6,%7}, {%8,%9}, {%0,%1,%2,%3};"
        : "+f"(c[0]), "+f"(c[1]), "+f"(c[2]), "+f"(c[3])
        : "r"(a[0]), "r"(a[1]), "r"(a[2]), "r"(a[3]), "r"(b[0]), "r"(b[1]));
}

__device__ __forceinline__ void load_chunk(
    uint32_t smA, uint32_t smB,
    const __half* __restrict__ A, const __half* __restrict__ B,
    size_t rowA0, size_t rowB0, int K3, int k0, int tid)
{
#pragma unroll
    for (int i = 0; i < 4; i++) {
        int u = tid + (i << 8);
        int row = u >> 3, kk = u & 7;
        uint32_t off = (uint32_t)(row * 128 + kk * 16);
        uint32_t sw = off ^ ((off >> 3) & 0x70);
        cp16(smA + sw, A + (rowA0 + row) * (size_t)K3 + k0 + kk * 8);
        cp16(smB + sw, B + (rowB0 + row) * (size_t)K3 + k0 + kk * 8);
    }
}

__global__ __launch_bounds__(256) void gemm_mma(
    const __half* __restrict__ A, const __half* __restrict__ B,
    const float* __restrict__ bias,
    float* __restrict__ Cf, __half* __restrict__ Ch, __half* __restrict__ Ccat,
    int M, int N, int K3, int relu)
{
    extern __shared__ __align__(128) char smem[];
    uint32_t sbase = smem_u32(smem);

    int tid = threadIdx.x, lane = tid & 31, wid = tid >> 5;
    int warpM = wid >> 2, warpN = wid & 3;
    int tN = blockIdx.x, tM = blockIdx.y;
    size_t rowA0 = (size_t)tM * 128;
    size_t rowB0 = (size_t)tN * 128;
    int nch = K3 >> 6;

    float acc[4][4][4];
#pragma unroll
    for (int i = 0; i < 4; i++)
#pragma unroll
        for (int j = 0; j < 4; j++)
#pragma unroll
            for (int t = 0; t < 4; t++) acc[i][j][t] = 0.f;

    // prologue: prefetch chunks 0,1 into stages 0,1
    load_chunk(sbase, sbase + 16384, A, B, rowA0, rowB0, K3, 0, tid);
    asm volatile("cp.async.commit_group;" ::: "memory");
    load_chunk(sbase + 32768, sbase + 49152, A, B, rowA0, rowB0, K3, 64, tid);
    asm volatile("cp.async.commit_group;" ::: "memory");

    for (int c = 0; c < nch; c++) {
        if (c + 2 < nch) {
            uint32_t sb = sbase + (uint32_t)((c + 2) % 3) * 32768u;
            load_chunk(sb, sb + 16384, A, B, rowA0, rowB0, K3, (c + 2) << 6, tid);
            asm volatile("cp.async.commit_group;" ::: "memory");
            asm volatile("cp.async.wait_group 2;" ::: "memory");
        } else if (c + 1 < nch) {
            asm volatile("cp.async.wait_group 1;" ::: "memory");
        } else {
            asm volatile("cp.async.wait_group 0;" ::: "memory");
        }
        __syncthreads();

        uint32_t aB = sbase + (uint32_t)(c % 3) * 32768u;
        uint32_t bB = aB + 16384;
#pragma unroll
        for (int ks = 0; ks < 4; ks++) {
            uint32_t af[4][4], bf[4][2];
#pragma unroll
            for (int mf = 0; mf < 4; mf++) {
                int row = warpM * 64 + mf * 16 + (lane & 15);
                uint32_t off = (uint32_t)(row * 128 + ks * 32 + ((lane >> 4) << 4));
                off ^= (off >> 3) & 0x70;
                ldsm_x4(af[mf], aB + off);
            }
#pragma unroll
            for (int nf = 0; nf < 4; nf++) {
                int row = warpN * 32 + nf * 8 + (lane & 7);
                uint32_t off = (uint32_t)(row * 128 + ks * 32 + (((lane >> 3) & 1) << 4));
                off ^= (off >> 3) & 0x70;
                ldsm_x2(bf[nf], bB + off);
            }
#pragma unroll
            for (int mf = 0; mf < 4; mf++)
#pragma unroll
                for (int nf = 0; nf < 4; nf++)
                    mma16816(acc[mf][nf], af[mf], bf[nf]);
        }
        __syncthreads();
    }

    // epilogue
    int m0 = tM * 128 + warpM * 64;
    int n0 = tN * 128 + warpN * 32;
#pragma unroll
    for (int mf = 0; mf < 4; mf++) {
#pragma unroll
        for (int nf = 0; nf < 4; nf++) {
            int r = m0 + mf * 16 + (lane >> 2);
            int col = n0 + nf * 8 + ((lane & 3) << 1);
            float b0 = bias ? __ldg(bias + col) : 0.f;
            float b1 = bias ? __ldg(bias + col + 1) : 0.f;
            float v00 = acc[mf][nf][0] + b0, v01 = acc[mf][nf][1] + b1;
            float v10 = acc[mf][nf][2] + b0, v11 = acc[mf][nf][3] + b1;
            if (relu) {
                v00 = fmaxf(v00, 0.f); v01 = fmaxf(v01, 0.f);
                v10 = fmaxf(v10, 0.f); v11 = fmaxf(v11, 0.f);
            }
            if (Cf) {
                *(float2*)(Cf + (size_t)r * N + col) = make_float2(v00, v01);
                *(float2*)(Cf + (size_t)(r + 8) * N + col) = make_float2(v10, v11);
            }
            if (Ch) {
                __half2 h0 = __floats2half2_rn(v00, v01);
                __half2 h1 = __floats2half2_rn(v10, v11);
                *(__half2*)(Ch + (size_t)r * N + col) = h0;
                *(__half2*)(Ch + (size_t)(r + 8) * N + col) = h1;
            }
            if (Ccat) {
                __half h00 = __float2half_rn(v00), h01 = __float2half_rn(v01);
                __half h10 = __float2half_rn(v10), h11 = __float2half_rn(v11);
                uint32_t uh0 = pack_h2(h00, h01), uh1 = pack_h2(h10, h11);
                uint32_t ul0 = pack_h2(__float2half_rn(v00 - __half2float(h00)),
                                       __float2half_rn(v01 - __half2float(h01)));
                uint32_t ul1 = pack_h2(__float2half_rn(v10 - __half2float(h10)),
                                       __float2half_rn(v11 - __half2float(h11)));
                size_t b0a = (size_t)r * 3 * N + col;
                size_t b1a = (size_t)(r + 8) * 3 * N + col;
                *(uint32_t*)(Ccat + b0a) = uh0;
                *(uint32_t*)(Ccat + b0a + N) = ul0;
                *(uint32_t*)(Ccat + b0a + 2 * N) = uh0;
                *(uint32_t*)(Ccat + b1a) = uh1;
                *(uint32_t*)(Ccat + b1a + N) = ul1;
                *(uint32_t*)(Ccat + b1a + 2 * N) = uh1;
            }
        }
    }
}

// ---------------- fp32 -> cat fp16 converters ---------------------------------
__global__ __launch_bounds__(256) void cvt_cat3(
    const float* __restrict__ s, __half* __restrict__ d, int K, int n4)
{
    int i = blockIdx.x * blockDim.x + threadIdx.x;
    if (i >= n4) return;
    int i4 = i * 4;
    int row = i4 / K, col = i4 % K;
    float4 v = ((const float4*)s)[i];
    float vv[4] = {v.x, v.y, v.z, v.w};
    __half h[4], l[4];
#pragma unroll
    for (int j = 0; j < 4; j++) {
        h[j] = __float2half_rn(vv[j]);
        l[j] = __float2half_rn(vv[j] - __half2float(h[j]));
    }
    size_t base = (size_t)row * 3 * K + col;
    uint2 uh = make_uint2(pack_h2(h[0], h[1]), pack_h2(h[2], h[3]));
    uint2 ul = make_uint2(pack_h2(l[0], l[1]), pack_h2(l[2], l[3]));
    *(uint2*)(d + base) = uh;
    *(uint2*)(d + base + K) = ul;
    *(uint2*)(d + base + 2 * K) = uh;
}

__global__ __launch_bounds__(256) void cvt_cat2(
    const float* __restrict__ s, __half* __restrict__ d, int K, int n4)
{
    int i = blockIdx.x * blockDim.x + threadIdx.x;
    if (i >= n4) return;
    int i4 = i * 4;
    int row = i4 / K, col = i4 % K;
    float4 v = ((const float4*)s)[i];
    float vv[4] = {v.x, v.y, v.z, v.w};
    __half h[4], l[4];
#pragma unroll
    for (int j = 0; j < 4; j++) {
        h[j] = __float2half_rn(vv[j]);
        l[j] = __float2half_rn(vv[j] - __half2float(h[j]));
    }
    size_t base = (size_t)row * 2 * K + col;
    *(uint2*)(d + base) = make_uint2(pack_h2(h[0], h[1]), pack_h2(h[2], h[3]));
    *(uint2*)(d + base + K) = make_uint2(pack_h2(l[0], l[1]), pack_h2(l[2], l[3]));
}

// ---------------- weight transpose + cat convert -------------------------------
// W [K,N] row-major -> out [N, stride]; 3-cat [hi|hi|lo] or 2-cat [hi|hi]
__global__ void tconv(const float* __restrict__ W, __half* __restrict__ out,
                      int K, int N, int cat2)
{
    __shared__ float t[32][33];
    int tx = threadIdx.x, ty = threadIdx.y;       // 32 x 8
    int n0 = blockIdx.x * 32, k0 = blockIdx.y * 32;
#pragma unroll
    for (int r = 0; r < 4; r++)
        t[ty + 8 * r][tx] = W[(size_t)(k0 + ty + 8 * r) * N + n0 + tx];
    __syncthreads();
    int stride = cat2 ? 2 * K : 3 * K;
#pragma unroll
    for (int r = 0; r < 4; r++) {
        int nl = ty + 8 * r;
        float v = t[tx][nl];
        size_t o = (size_t)(n0 + nl) * stride + k0 + tx;
        __half h = __float2half_rn(v);
        out[o] = h;
        out[o + K] = h;
        if (!cat2) out[o + 2 * K] = __float2half_rn(v - __half2float(h));
    }
}

// ---------------- bias pack for fused QKVS -------------------------------------
__global__ void pack_bias(const float* __restrict__ bq, const float* __restrict__ bk,
                          const float* __restrict__ bv, const float* __restrict__ bs)
{
    int b = blockIdx.x, t = threadIdx.x;
    float v = (t < 256) ? bq[b * 256 + t]
            : (t < 512) ? bk[b * 256 + t - 256]
            : (t < 768) ? bv[b * 256 + t - 512]
                        : bs[b * 256 + t - 768];
    g_bqkvs[b * 1024 + t] = v;
}

// ---------------- per-block init: zero msg accum + softmax state ---------------
__global__ __launch_bounds__(256) void init_kernel() {
    int i = blockIdx.x * blockDim.x + threadIdx.x;
    if (i < LN_CNT / 4) ((float4*)g_out)[i] = make_float4(0.f, 0.f, 0.f, 0.f);
    if (i < N_NODES * HEADS) { g_amax[i] = 0u; g_denom[i] = 0.f; }
    if (i < 4) g_red[i] = 0.0;
}

// ---------------- attention pass 1: logits + segment max -----------------------
__global__ __launch_bounds__(256) void edge_alpha(
    const int* __restrict__ ei, const float* __restrict__ xdist)
{
    int w = (blockIdx.x * blockDim.x + threadIdx.x) >> 5;
    int lane = threadIdx.x & 31;
    if (w >= N_EDGES) return;
    int src = ei[w], dst = ei[N_EDGES + w];

    const float4* qr = (const float4*)(g_qkvs + (size_t)dst * 1024) + lane * 2;
    const float4* kr = (const float4*)(g_qkvs + (size_t)src * 1024 + 256) + lane * 2;
    int4 ev = *(const int4*)(g_e_h + (size_t)w * DIM + lane * 8);
    __half2* eh = (__half2*)&ev;
    float2 e0 = __half22float2(eh[0]), e1 = __half22float2(eh[1]);
    float2 e2 = __half22float2(eh[2]), e3 = __half22float2(eh[3]);

    float4 q0 = qr[0], q1 = qr[1], k0 = kr[0], k1 = kr[1];
    float p = 0.f;
    p = fmaf(q0.x, k0.x + e0.x, p);
    p = fmaf(q0.y, k0.y + e0.y, p);
    p = fmaf(q0.z, k0.z + e1.x, p);
    p = fmaf(q0.w, k0.w + e1.y, p);
    p = fmaf(q1.x, k1.x + e2.x, p);
    p = fmaf(q1.y, k1.y + e2.y, p);
    p = fmaf(q1.z, k1.z + e3.x, p);
    p = fmaf(q1.w, k1.w + e3.y, p);
    p += __shfl_xor_sync(0xffffffffu, p, 1);
    p += __shfl_xor_sync(0xffffffffu, p, 2);
    if ((lane & 3) == 0) {
        int h = lane >> 2;
        float a = p * (1.0f / xdist[w]) * RSQRT_DH;
        g_alpha[(size_t)w * HEADS + h] = a;
        atomicMax(&g_amax[dst * HEADS + h], fenc(a));
    }
}

// ---------------- attention pass 2: exp + denom + unnormalized message ---------
__global__ __launch_bounds__(256) void edge_expmsg(const int* __restrict__ ei)
{
    int w = (blockIdx.x * blockDim.x + threadIdx.x) >> 5;
    int lane = threadIdx.x & 31;
    if (w >= N_EDGES) return;
    int src = ei[w], dst = ei[N_EDGES + w];
    int h = lane >> 2;

    float a = g_alpha[(size_t)w * HEADS + h];
    float m = fdec(g_amax[dst * HEADS + h]);
    float ex = __expf(a - m);
    if ((lane & 3) == 0) atomicAdd(&g_denom[dst * HEADS + h], ex);

    const float4* vr = (const float4*)(g_qkvs + (size_t)src * 1024 + 512) + lane * 2;
    int4 evi = *(const int4*)(g_e_h + (size_t)w * DIM + lane * 8);
    __half2* eh = (__half2*)&evi;
    float2 e0 = __half22float2(eh[0]), e1 = __half22float2(eh[1]);
    float2 e2 = __half22float2(eh[2]), e3 = __half22float2(eh[3]);
    float4 v0 = vr[0], v1 = vr[1];

    float* op = g_out + (size_t)dst * DIM + lane * 8;
    float4 r0 = make_float4((v0.x + e0.x) * ex, (v0.y + e0.y) * ex,
                            (v0.z + e1.x) * ex, (v0.w + e1.y) * ex);
    float4 r1 = make_float4((v1.x + e2.x) * ex, (v1.y + e2.y) * ex,
                            (v1.z + e3.x) * ex, (v1.w + e3.y) * ex);
    red_add_v4(op, r0);
    red_add_v4(op + 4, r1);
}

// ---------------- LN1 residual: x + skip + msg/denom, + DP reduction -----------
__global__ __launch_bounds__(256) void resred_attn(
    const float* __restrict__ x, float* __restrict__ y, double* __restrict__ red)
{
    int i = blockIdx.x * blockDim.x + threadIdx.x;
    int i4 = i * 4;
    int row = i4 >> 8, c = i4 & 255, h = c >> 5;
    float4 xv = ((const float4*)x)[i];
    float4 sk = *(const float4*)(g_qkvs + (size_t)row * 1024 + 768 + c);
    float4 mg = ((const float4*)g_out)[i];
    float inv = 1.0f / (g_denom[row * HEADS + h] + 1e-16f);
    float4 s = make_float4(xv.x + sk.x + mg.x * inv, xv.y + sk.y + mg.y * inv,
                           xv.z + sk.z + mg.z * inv, xv.w + sk.w + mg.w * inv);
    ((float4*)y)[i] = s;

    double ls = (double)s.x + (double)s.y + (double)s.z + (double)s.w;
    double lq = (double)s.x * s.x + (double)s.y * s.y +
                (double)s.z * s.z + (double)s.w * s.w;
#pragma unroll
    for (int o = 16; o > 0; o >>= 1) {
        ls += __shfl_down_sync(0xffffffffu, ls, o);
        lq += __shfl_down_sync(0xffffffffu, lq, o);
    }
    __shared__ double shs[8], shq[8];
    int wid = threadIdx.x >> 5, lane = threadIdx.x & 31;
    if (lane == 0) { shs[wid] = ls; shq[wid] = lq; }
    __syncthreads();
    if (threadIdx.x == 0) {
        double ts = 0, tq = 0;
#pragma unroll
        for (int k = 0; k < 8; k++) { ts += shs[k]; tq += shq[k]; }
        atomicAdd(&red[0], ts);
        atomicAdd(&red[1], tq);
    }
}

// ---------------- plain residual + DP reduction --------------------------------
__global__ __launch_bounds__(256) void resred(
    const float* __restrict__ a, const float* __restrict__ b,
    float* __restrict__ y, double* __restrict__ red)
{
    int i = blockIdx.x * blockDim.x + threadIdx.x;
    float4 av = ((const float4*)a)[i];
    float4 bv = ((const float4*)b)[i];
    float4 s = make_float4(av.x + bv.x, av.y + bv.y, av.z + bv.z, av.w + bv.w);
    ((float4*)y)[i] = s;

    double ls = (double)s.x + (double)s.y + (double)s.z + (double)s.w;
    double lq = (double)s.x * s.x + (double)s.y * s.y +
                (double)s.z * s.z + (double)s.w * s.w;
#pragma unroll
    for (int o = 16; o > 0; o >>= 1) {
        ls += __shfl_down_sync(0xffffffffu, ls, o);
        lq += __shfl_down_sync(0xffffffffu, lq, o);
    }
    __shared__ double shs[8], shq[8];
    int wid = threadIdx.x >> 5, lane = threadIdx.x & 31;
    if (lane == 0) { shs[wid] = ls; shq[wid] = lq; }
    __syncthreads();
    if (threadIdx.x == 0) {
        double ts = 0, tq = 0;
#pragma unroll
        for (int k = 0; k < 8; k++) { ts += shs[k]; tq += shq[k]; }
        atomicAdd(&red[0], ts);
        atomicAdd(&red[1], tq);
    }
}

// ---------------- graph layernorm apply + 3-cat fp16 emit ----------------------
__global__ __launch_bounds__(256) void lnapply(
    const float* __restrict__ y, const float* __restrict__ g,
    const float* __restrict__ b, float* __restrict__ o,
    __half* __restrict__ ocat, const double* __restrict__ red)
{
    int i = blockIdx.x * blockDim.x + threadIdx.x;
    double mean = red[0] / (double)LN_CNT;
    double var  = red[1] / (double)LN_CNT - mean * mean;
    if (var < 0) var = 0;
    float inv = 1.0f / ((float)sqrt(var) + LN_EPS);
    float mu = (float)mean;

    int i4 = i * 4;
    int c = i4 % DIM;
    int row = i4 / DIM;
    float4 yv = ((const float4*)y)[i];
    float4 gv = *(const float4*)(g + c);
    float4 bv = *(const float4*)(b + c);
    float4 r;
    r.x = (yv.x - mu) * inv * gv.x + bv.x;
    r.y = (yv.y - mu) * inv * gv.y + bv.y;
    r.z = (yv.z - mu) * inv * gv.z + bv.z;
    r.w = (yv.w - mu) * inv * gv.w + bv.w;
    ((float4*)o)[i] = r;

    float vv[4] = {r.x, r.y, r.z, r.w};
    __half h[4], l[4];
#pragma unroll
    for (int j = 0; j < 4; j++) {
        h[j] = __float2half_rn(vv[j]);
        l[j] = __float2half_rn(vv[j] - __half2float(h[j]));
    }
    size_t base = (size_t)row * 3 * DIM + c;
    uint2 uh = make_uint2(pack_h2(h[0], h[1]), pack_h2(h[2], h[3]));
    uint2 ul = make_uint2(pack_h2(l[0], l[1]), pack_h2(l[2], l[3]));
    *(uint2*)(ocat + base) = uh;
    *(uint2*)(ocat + base + DIM) = ul;
    *(uint2*)(ocat + base + 2 * DIM) = uh;
}

// ---------------- host orchestration -------------------------------------------
extern "C" void kernel_launch(void* const* d_in, const int* in_sizes, int n_in,
                              void* d_out, int out_size)
{
    const float* x_in   = (const float*)d_in[0];
    const int*   ei     = (const int*)d_in[1];
    const float* x_edge = (const float*)d_in[2];
    const float* x_dist = (const float*)d_in[3];
    const float* Wq_a   = (const float*)d_in[4];
    const float* bq_a   = (const float*)d_in[5];
    const float* Wk_a   = (const float*)d_in[6];
    const float* bk_a   = (const float*)d_in[7];
    const float* Wv_a   = (const float*)d_in[8];
    const float* bv_a   = (const float*)d_in[9];
    const float* We_a   = (const float*)d_in[10];
    const float* Ws_a   = (const float*)d_in[11];
    const float* bs_a   = (const float*)d_in[12];
    const float* g1_a   = (const float*)d_in[13];
    const float* b1_a   = (const float*)d_in[14];
    const float* W1_a   = (const float*)d_in[15];
    const float* c1_a   = (const float*)d_in[16];
    const float* W2_a   = (const float*)d_in[17];
    const float* c2_a   = (const float*)d_in[18];
    const float* g2_a   = (const float*)d_in[19];
    const float* b2_a   = (const float*)d_in[20];

    static int smem_set = 0;
    if (!smem_set) {
        cudaFuncSetAttribute(gemm_mma, cudaFuncAttributeMaxDynamicSharedMemorySize,
                             GEMM_SMEM);
        smem_set = 1;
    }

    float *qkvs_, *out_, *y_, *x_, *bqkvs_;
    double* red_;
    __half *eh_, *xec_, *xc_, *yc_, *hc_, *wt_;
    cudaGetSymbolAddress((void**)&qkvs_, g_qkvs);
    cudaGetSymbolAddress((void**)&eh_,   g_e_h);
    cudaGetSymbolAddress((void**)&out_,  g_out);
    cudaGetSymbolAddress((void**)&y_,    g_y);
    cudaGetSymbolAddress((void**)&x_,    g_x);
    cudaGetSymbolAddress((void**)&red_,  g_red);
    cudaGetSymbolAddress((void**)&bqkvs_, g_bqkvs);
    cudaGetSymbolAddress((void**)&xec_,  g_xe_cat2);
    cudaGetSymbolAddress((void**)&xc_,   g_x_cat);
    cudaGetSymbolAddress((void**)&yc_,   g_y_cat);
    cudaGetSymbolAddress((void**)&hc_,   g_h_cat);
    cudaGetSymbolAddress((void**)&wt_,   g_wt_cat);

    const int elem4 = LN_CNT / 4;

    // one-time conversions
    cvt_cat3<<<(elem4 + 255) / 256, 256>>>(x_in, xc_, DIM, elem4);
    {
        int n4 = N_EDGES * DIM / 4;
        cvt_cat2<<<(n4 + 255) / 256, 256>>>(x_edge, xec_, DIM, n4);
    }
    pack_bias<<<3, 1024>>>(bq_a, bk_a, bv_a, bs_a);
    dim3 tb(32, 8);
    for (int b = 0; b < 3; b++) {
        size_t wb = (size_t)b * WB;
        __half* wq = wt_ + wb + OW_QKVS;
        tconv<<<dim3(8, 8),  tb>>>(Wq_a + (size_t)b * DIM * DIM, wq,                 DIM, DIM, 0);
        tconv<<<dim3(8, 8),  tb>>>(Wk_a + (size_t)b * DIM * DIM, wq + 256 * 768,     DIM, DIM, 0);
        tconv<<<dim3(8, 8),  tb>>>(Wv_a + (size_t)b * DIM * DIM, wq + 512 * 768,     DIM, DIM, 0);
        tconv<<<dim3(8, 8),  tb>>>(Ws_a + (size_t)b * DIM * DIM, wq + 768 * 768,     DIM, DIM, 0);
        tconv<<<dim3(8, 8),  tb>>>(We_a + (size_t)b * DIM * DIM, wt_ + wb + OW_E,    DIM, DIM, 1);
        tconv<<<dim3(32, 8), tb>>>(W1_a + (size_t)b * DIM * HID, wt_ + wb + OW_1,    DIM, HID, 0);
        tconv<<<dim3(8, 32), tb>>>(W2_a + (size_t)b * HID * DIM, wt_ + wb + OW_2,    HID, DIM, 0);
    }

    const float* xcur = x_in;
    for (int blk = 0; blk < 3; blk++) {
        size_t wb = (size_t)blk * WB;
        const float* g1 = g1_a + blk * DIM;
        const float* b1 = b1_a + blk * DIM;
        const float* c1 = c1_a + blk * HID;
        const float* c2 = c2_a + blk * DIM;
        const float* g2 = g2_a + blk * DIM;
        const float* b2 = b2_a + blk * DIM;

        init_kernel<<<(elem4 + 255) / 256, 256>>>();

        // fused Q|K|V|S projection (N=1024) and 2-cat edge projection (fp16 out)
        gemm_mma<<<dim3(8, 125), 256, GEMM_SMEM>>>(
            xc_, wt_ + wb + OW_QKVS, bqkvs_ + blk * 1024,
            qkvs_, nullptr, nullptr, N_NODES, 1024, 768, 0);
        gemm_mma<<<dim3(2, 2000), 256, GEMM_SMEM>>>(
            xec_, wt_ + wb + OW_E, nullptr,
            nullptr, eh_, nullptr, N_EDGES, DIM, 512, 0);

        edge_alpha<<<N_EDGES / 8, 256>>>(ei, x_dist);
        edge_expmsg<<<N_EDGES / 8, 256>>>(ei);

        // residual + graph LN 1
        resred_attn<<<elem4 / 256, 256>>>(xcur, y_, red_ + 0);
        lnapply<<<elem4 / 256, 256>>>(y_, g1, b1, y_, yc_, red_ + 0);

        // FFN (FFN1 emits 3-cat hidden directly)
        gemm_mma<<<dim3(8, 125), 256, GEMM_SMEM>>>(
            yc_, wt_ + wb + OW_1, c1,
            nullptr, nullptr, hc_, N_NODES, HID, 768, 1);
        gemm_mma<<<dim3(2, 125), 256, GEMM_SMEM>>>(
            hc_, wt_ + wb + OW_2, c2,
            out_, nullptr, nullptr, N_NODES, DIM, 3072, 0);

        // residual + graph LN 2
        resred<<<elem4 / 256, 256>>>(y_, out_, out_, red_ + 2);
        float* xdst = (blk == 2) ? (float*)d_out : x_;
        lnapply<<<elem4 / 256, 256>>>(out_, g2, b2, xdst, xc_, red_ + 2);

        xcur = x_;
    }
}

// round 7
// speedup vs baseline: 2.6695x; 1.2438x over previous
#include <cuda_runtime.h>
#include <cuda_fp16.h>
#include <math.h>
#include <stdint.h>

#define N_NODES 16000
#define N_EDGES 256000
#define DIM 256
#define HEADS 8
#define HID 1024
#define LN_CNT (N_NODES * DIM)
#define LN_EPS 1e-5f
#define RSQRT_DH 0.17677669529663687f

// cat-weight table offsets (halves, per transformer block)
#define OW_QKVS 0              // [1024, 768]  3-cat
#define OW_E    786432         // [256, 256]   plain fp16
#define OW_1    851968         // [1024, 768]  3-cat
#define OW_2    1638400        // [256, 3072]  3-cat
#define WB      2424832

// ---------------- scratch (static device globals; no allocation) -------------
__device__ float    g_qkvs[(size_t)N_NODES * 1024];        // q|k|v|skip per node
__device__ __half   g_e_h3[3 * (size_t)N_EDGES * DIM];     // 393 MB: e for all blocks
__device__ float    g_out[N_NODES * DIM];
__device__ float    g_y[N_NODES * DIM];
__device__ float    g_x[N_NODES * DIM];
__device__ float    g_denom[N_NODES * HEADS];
__device__ double   g_red[4];
__device__ float    g_bqkvs[3 * 1024];
__device__ __half   g_xe_h[(size_t)N_EDGES * DIM];         // 131 MB plain fp16
__device__ __half   g_x_cat[(size_t)N_NODES * 3 * DIM];    // [hi|lo|hi]
__device__ __half   g_y_cat[(size_t)N_NODES * 3 * DIM];
__device__ __half   g_h_cat[(size_t)N_NODES * 3 * HID];
__device__ __half   g_wt_cat[3 * WB];

// ---------------- helpers -----------------------------------------------------
__device__ __forceinline__ uint32_t smem_u32(const void* p) {
    uint32_t a;
    asm("{ .reg .u64 t; cvta.to.shared.u64 t, %1; cvt.u32.u64 %0, t; }"
        : "=r"(a) : "l"(p));
    return a;
}
__device__ __forceinline__ void red_add_v4(float* addr, float4 v) {
    asm volatile("red.global.add.v4.f32 [%0], {%1,%2,%3,%4};"
                 :: "l"(addr), "f"(v.x), "f"(v.y), "f"(v.z), "f"(v.w) : "memory");
}
__device__ __forceinline__ uint32_t pack_h2(__half a, __half b) {
    __half2 h2 = __halves2half2(a, b);
    return *(uint32_t*)&h2;
}
__device__ __forceinline__ void cp16(uint32_t dst, const void* src) {
    asm volatile("cp.async.cg.shared.global [%0], [%1], 16;"
                 :: "r"(dst), "l"(src) : "memory");
}
__device__ __forceinline__ void ldsm_x4(uint32_t* r, uint32_t addr) {
    asm volatile("ldmatrix.sync.aligned.m8n8.x4.shared.b16 {%0,%1,%2,%3}, [%4];"
                 : "=r"(r[0]), "=r"(r[1]), "=r"(r[2]), "=r"(r[3]) : "r"(addr));
}
__device__ __forceinline__ void mma16816(float* c, const uint32_t* a, uint32_t b0, uint32_t b1) {
    asm volatile(
        "mma.sync.aligned.m16n8k16.row.col.f32.f16.f16.f32 "
        "{%0,%1,%2,%3}, {%4,%5,%6,%7}, {%8,%9}, {%0,%1,%2,%3};"
        : "+f"(c[0]), "+f"(c[1]), "+f"(c[2]), "+f"(c[3])
        : "r"(a[0]), "r"(a[1]), "r"(a[2]), "r"(a[3]), "r"(b0), "r"(b1));
}

// ================== node GEMM: CTA 128x128, 4 warps (2x2), warp 64x64 =========
// C[M,N] = A[M,K3] @ B[N,K3]^T (+bias, relu); 3-stage cp.async, K-chunk 64.
#define NG_SMEM 98304

__device__ __forceinline__ void load_chunk_n(
    uint32_t st, const __half* __restrict__ A, const __half* __restrict__ B,
    size_t rowA0, size_t rowB0, int K3, int k0, int tid)
{
#pragma unroll
    for (int i = 0; i < 8; i++) {
        int u = tid + (i << 7);
        int row = u >> 3, kk = u & 7;
        uint32_t off = (uint32_t)(row * 128 + kk * 16);
        uint32_t sw = off ^ ((off >> 3) & 0x70);
        cp16(st + sw, A + (rowA0 + row) * (size_t)K3 + k0 + kk * 8);
        cp16(st + 16384 + sw, B + (rowB0 + row) * (size_t)K3 + k0 + kk * 8);
    }
}

__global__ __launch_bounds__(128) void gemm_mma(
    const __half* __restrict__ A, const __half* __restrict__ B,
    const float* __restrict__ bias,
    float* __restrict__ Cf, __half* __restrict__ Ccat,
    int M, int N, int K3, int relu)
{
    extern __shared__ __align__(128) char smem[];
    uint32_t sbase = smem_u32(smem);

    int tid = threadIdx.x, lane = tid & 31, wid = tid >> 5;
    int warpM = wid >> 1, warpN = wid & 1;
    int tN = blockIdx.x, tM = blockIdx.y;
    size_t rowA0 = (size_t)tM * 128;
    size_t rowB0 = (size_t)tN * 128;
    int nch = K3 >> 6;

    float acc[4][8][4];
#pragma unroll
    for (int i = 0; i < 4; i++)
#pragma unroll
        for (int j = 0; j < 8; j++)
#pragma unroll
            for (int t = 0; t < 4; t++) acc[i][j][t] = 0.f;

    load_chunk_n(sbase, A, B, rowA0, rowB0, K3, 0, tid);
    asm volatile("cp.async.commit_group;" ::: "memory");
    load_chunk_n(sbase + 32768, A, B, rowA0, rowB0, K3, 64, tid);
    asm volatile("cp.async.commit_group;" ::: "memory");

    for (int c = 0; c < nch; c++) {
        if (c + 2 < nch) {
            uint32_t sb = sbase + (uint32_t)((c + 2) % 3) * 32768u;
            load_chunk_n(sb, A, B, rowA0, rowB0, K3, (c + 2) << 6, tid);
            asm volatile("cp.async.commit_group;" ::: "memory");
            asm volatile("cp.async.wait_group 2;" ::: "memory");
        } else if (c + 1 < nch) {
            asm volatile("cp.async.wait_group 1;" ::: "memory");
        } else {
            asm volatile("cp.async.wait_group 0;" ::: "memory");
        }
        __syncthreads();

        uint32_t aB = sbase + (uint32_t)(c % 3) * 32768u;
        uint32_t bB = aB + 16384;
#pragma unroll
        for (int ks = 0; ks < 4; ks++) {
            uint32_t af[4][4], bf[4][4];
#pragma unroll
            for (int mf = 0; mf < 4; mf++) {
                int row = warpM * 64 + mf * 16 + (lane & 15);
                uint32_t off = (uint32_t)(row * 128 + ks * 32 + ((lane >> 4) << 4));
                off ^= (off >> 3) & 0x70;
                ldsm_x4(af[mf], aB + off);
            }
#pragma unroll
            for (int nf2 = 0; nf2 < 4; nf2++) {
                int row = warpN * 64 + nf2 * 16 + (lane & 15);
                uint32_t off = (uint32_t)(row * 128 + ks * 32 + ((lane >> 4) << 4));
                off ^= (off >> 3) & 0x70;
                ldsm_x4(bf[nf2], bB + off);
            }
#pragma unroll
            for (int mf = 0; mf < 4; mf++)
#pragma unroll
                for (int nf2 = 0; nf2 < 4; nf2++) {
                    mma16816(acc[mf][nf2 * 2],     af[mf], bf[nf2][0], bf[nf2][2]);
                    mma16816(acc[mf][nf2 * 2 + 1], af[mf], bf[nf2][1], bf[nf2][3]);
                }
        }
        __syncthreads();
    }

    int m0 = tM * 128 + warpM * 64;
    int n0 = tN * 128 + warpN * 64;
#pragma unroll
    for (int mf = 0; mf < 4; mf++) {
#pragma unroll
        for (int nf = 0; nf < 8; nf++) {
            int r = m0 + mf * 16 + (lane >> 2);
            int col = n0 + nf * 8 + ((lane & 3) << 1);
            float b0 = bias ? __ldg(bias + col) : 0.f;
            float b1 = bias ? __ldg(bias + col + 1) : 0.f;
            float v00 = acc[mf][nf][0] + b0, v01 = acc[mf][nf][1] + b1;
            float v10 = acc[mf][nf][2] + b0, v11 = acc[mf][nf][3] + b1;
            if (relu) {
                v00 = fmaxf(v00, 0.f); v01 = fmaxf(v01, 0.f);
                v10 = fmaxf(v10, 0.f); v11 = fmaxf(v11, 0.f);
            }
            if (Cf) {
                *(float2*)(Cf + (size_t)r * N + col) = make_float2(v00, v01);
                *(float2*)(Cf + (size_t)(r + 8) * N + col) = make_float2(v10, v11);
            }
            if (Ccat) {
                __half h00 = __float2half_rn(v00), h01 = __float2half_rn(v01);
                __half h10 = __float2half_rn(v10), h11 = __float2half_rn(v11);
                uint32_t uh0 = pack_h2(h00, h01), uh1 = pack_h2(h10, h11);
                uint32_t ul0 = pack_h2(__float2half_rn(v00 - __half2float(h00)),
                                       __float2half_rn(v01 - __half2float(h01)));
                uint32_t ul1 = pack_h2(__float2half_rn(v10 - __half2float(h10)),
                                       __float2half_rn(v11 - __half2float(h11)));
                size_t b0a = (size_t)r * 3 * N + col;
                size_t b1a = (size_t)(r + 8) * 3 * N + col;
                *(uint32_t*)(Ccat + b0a) = uh0;
                *(uint32_t*)(Ccat + b0a + N) = ul0;
                *(uint32_t*)(Ccat + b0a + 2 * N) = uh0;
                *(uint32_t*)(Ccat + b1a) = uh1;
                *(uint32_t*)(Ccat + b1a + N) = ul1;
                *(uint32_t*)(Ccat + b1a + 2 * N) = uh1;
            }
        }
    }
}

// ================== edge GEMM: A-resident, all 3 blocks in one pass ===========
// A tile 128x256 halves fully in SMEM (64KB); loop over 6 weight N-tiles.
#define EG_SMEM 98304

__global__ __launch_bounds__(128) void gemm_edge(
    const __half* __restrict__ XE, const __half* __restrict__ WT,
    __half* __restrict__ EH)
{
    extern __shared__ __align__(128) char smem[];
    uint32_t sbase = smem_u32(smem);
    uint32_t bbase = sbase + 65536;

    int tid = threadIdx.x, lane = tid & 31, wid = tid >> 5;
    int warpM = wid >> 1, warpN = wid & 1;
    size_t rowA0 = (size_t)blockIdx.x * 128;

    // preload all of A (4 chunks of 64 halves)
#pragma unroll
    for (int ch = 0; ch < 4; ch++) {
#pragma unroll
        for (int i = 0; i < 8; i++) {
            int u = tid + (i << 7);
            int row = u >> 3, kk = u & 7;
            uint32_t off = (uint32_t)(row * 128 + kk * 16);
            uint32_t sw = off ^ ((off >> 3) & 0x70);
            cp16(sbase + ch * 16384 + sw, XE + (rowA0 + row) * 256 + ch * 64 + kk * 8);
        }
    }
    // preload B(0)
    {
#pragma unroll
        for (int i = 0; i < 8; i++) {
            int u = tid + (i << 7);
            int row = u >> 3, kk = u & 7;
            uint32_t off = (uint32_t)(row * 128 + kk * 16);
            uint32_t sw = off ^ ((off >> 3) & 0x70);
            cp16(bbase + sw, WT + OW_E + (size_t)row * 256 + kk * 8);
        }
    }
    asm volatile("cp.async.commit_group;" ::: "memory");

    float acc[4][8][4];
#pragma unroll
    for (int i = 0; i < 4; i++)
#pragma unroll
        for (int j = 0; j < 8; j++)
#pragma unroll
            for (int t = 0; t < 4; t++) acc[i][j][t] = 0.f;

    for (int it = 0; it < 24; it++) {
        if (it < 23) {
            int j = it + 1;
            int wt = j >> 2, ck = j & 3;
            int blkj = wt >> 1, nh = wt & 1;
            const __half* Bp = WT + (size_t)blkj * WB + OW_E;
            uint32_t bb = bbase + (uint32_t)(j & 1) * 16384u;
#pragma unroll
            for (int i = 0; i < 8; i++) {
                int u = tid + (i << 7);
                int row = u >> 3, kk = u & 7;
                uint32_t off = (uint32_t)(row * 128 + kk * 16);
                uint32_t sw = off ^ ((off >> 3) & 0x70);
                cp16(bb + sw, Bp + (size_t)(nh * 128 + row) * 256 + ck * 64 + kk * 8);
            }
            asm volatile("cp.async.commit_group;" ::: "memory");
            asm volatile("cp.async.wait_group 1;" ::: "memory");
        } else {
            asm volatile("cp.async.wait_group 0;" ::: "memory");
        }
        __syncthreads();

        int ck = it & 3;
        uint32_t aB = sbase + (uint32_t)ck * 16384u;
        uint32_t bB = bbase + (uint32_t)(it & 1) * 16384u;
#pragma unroll
        for (int ks = 0; ks < 4; ks++) {
            uint32_t af[4][4], bf[4][4];
#pragma unroll
            for (int mf = 0; mf < 4; mf++) {
                int row = warpM * 64 + mf * 16 + (lane & 15);
                uint32_t off = (uint32_t)(row * 128 + ks * 32 + ((lane >> 4) << 4));
                off ^= (off >> 3) & 0x70;
                ldsm_x4(af[mf], aB + off);
            }
#pragma unroll
            for (int nf2 = 0; nf2 < 4; nf2++) {
                int row = warpN * 64 + nf2 * 16 + (lane & 15);
                uint32_t off = (uint32_t)(row * 128 + ks * 32 + ((lane >> 4) << 4));
                off ^= (off >> 3) & 0x70;
                ldsm_x4(bf[nf2], bB + off);
            }
#pragma unroll
            for (int mf = 0; mf < 4; mf++)
#pragma unroll
                for (int nf2 = 0; nf2 < 4; nf2++) {
                    mma16816(acc[mf][nf2 * 2],     af[mf], bf[nf2][0], bf[nf2][2]);
                    mma16816(acc[mf][nf2 * 2 + 1], af[mf], bf[nf2][1], bf[nf2][3]);
                }
        }
        __syncthreads();

        if (ck == 3) {
            int wt = it >> 2;
            int blk = wt >> 1, nh = wt & 1;
            __half* out = EH + (size_t)blk * N_EDGES * DIM;
#pragma unroll
            for (int mf = 0; mf < 4; mf++) {
#pragma unroll
                for (int nf = 0; nf < 8; nf++) {
                    int r = (int)rowA0 + warpM * 64 + mf * 16 + (lane >> 2);
                    int col = nh * 128 + warpN * 64 + nf * 8 + ((lane & 3) << 1);
                    *(__half2*)(out + (size_t)r * DIM + col) =
                        __floats2half2_rn(acc[mf][nf][0], acc[mf][nf][1]);
                    *(__half2*)(out + (size_t)(r + 8) * DIM + col) =
                        __floats2half2_rn(acc[mf][nf][2], acc[mf][nf][3]);
#pragma unroll
                    for (int t = 0; t < 4; t++) acc[mf][nf][t] = 0.f;
                }
            }
        }
    }
}

// ---------------- converters ---------------------------------------------------
__global__ __launch_bounds__(256) void cvt_cat3(
    const float* __restrict__ s, __half* __restrict__ d, int K, int n4)
{
    int i = blockIdx.x * blockDim.x + threadIdx.x;
    if (i >= n4) return;
    int i4 = i * 4;
    int row = i4 / K, col = i4 % K;
    float4 v = ((const float4*)s)[i];
    float vv[4] = {v.x, v.y, v.z, v.w};
    __half h[4], l[4];
#pragma unroll
    for (int j = 0; j < 4; j++) {
        h[j] = __float2half_rn(vv[j]);
        l[j] = __float2half_rn(vv[j] - __half2float(h[j]));
    }
    size_t base = (size_t)row * 3 * K + col;
    uint2 uh = make_uint2(pack_h2(h[0], h[1]), pack_h2(h[2], h[3]));
    uint2 ul = make_uint2(pack_h2(l[0], l[1]), pack_h2(l[2], l[3]));
    *(uint2*)(d + base) = uh;
    *(uint2*)(d + base + K) = ul;
    *(uint2*)(d + base + 2 * K) = uh;
}

__global__ __launch_bounds__(256) void cvt_h(
    const float* __restrict__ s, __half* __restrict__ d, int n4)
{
    int i = blockIdx.x * blockDim.x + threadIdx.x;
    if (i >= n4) return;
    float4 v = ((const float4*)s)[i];
    *(uint2*)(d + (size_t)i * 4) =
        make_uint2(pack_h2(__float2half_rn(v.x), __float2half_rn(v.y)),
                   pack_h2(__float2half_rn(v.z), __float2half_rn(v.w)));
}

// ---------------- weight transpose + cat convert -------------------------------
// W [K,N] row-major -> out [N, stride]; cat=3: [hi|hi|lo], cat=1: plain fp16
__global__ void tconv(const float* __restrict__ W, __half* __restrict__ out,
                      int K, int N, int cat)
{
    __shared__ float t[32][33];
    int tx = threadIdx.x, ty = threadIdx.y;       // 32 x 8
    int n0 = blockIdx.x * 32, k0 = blockIdx.y * 32;
#pragma unroll
    for (int r = 0; r < 4; r++)
        t[ty + 8 * r][tx] = W[(size_t)(k0 + ty + 8 * r) * N + n0 + tx];
    __syncthreads();
    int stride = cat * K;
#pragma unroll
    for (int r = 0; r < 4; r++) {
        int nl = ty + 8 * r;
        float v = t[tx][nl];
        size_t o = (size_t)(n0 + nl) * stride + k0 + tx;
        __half h = __float2half_rn(v);
        out[o] = h;
        if (cat == 3) {
            out[o + K] = h;
            out[o + 2 * K] = __float2half_rn(v - __half2float(h));
        }
    }
}

// ---------------- bias pack for fused QKVS -------------------------------------
__global__ void pack_bias(const float* __restrict__ bq, const float* __restrict__ bk,
                          const float* __restrict__ bv, const float* __restrict__ bs)
{
    int b = blockIdx.x, t = threadIdx.x;
    float v = (t < 256) ? bq[b * 256 + t]
            : (t < 512) ? bk[b * 256 + t - 256]
            : (t < 768) ? bv[b * 256 + t - 512]
                        : bs[b * 256 + t - 768];
    g_bqkvs[b * 1024 + t] = v;
}

// ---------------- per-block init: zero msg accum + denom + red -----------------
__global__ __launch_bounds__(256) void init_kernel() {
    int i = blockIdx.x * blockDim.x + threadIdx.x;
    if (i < LN_CNT / 4) ((float4*)g_out)[i] = make_float4(0.f, 0.f, 0.f, 0.f);
    if (i < N_NODES * HEADS) g_denom[i] = 0.f;
    if (i < 4) g_red[i] = 0.0;
}

// ---------------- fused attention: logits + exp + denom + message --------------
__global__ __launch_bounds__(256) void edge_attn(
    const int* __restrict__ ei, const float* __restrict__ xdist,
    const __half* __restrict__ eh)
{
    int w = (blockIdx.x * blockDim.x + threadIdx.x) >> 5;
    int lane = threadIdx.x & 31;
    if (w >= N_EDGES) return;
    int src = ei[w], dst = ei[N_EDGES + w];
    int h = lane >> 2;

    const float4* qr = (const float4*)(g_qkvs + (size_t)dst * 1024) + lane * 2;
    const float4* kr = (const float4*)(g_qkvs + (size_t)src * 1024 + 256) + lane * 2;
    const float4* vr = (const float4*)(g_qkvs + (size_t)src * 1024 + 512) + lane * 2;
    int4 evi = *(const int4*)(eh + (size_t)w * DIM + lane * 8);
    __half2* ehp = (__half2*)&evi;
    float2 e0 = __half22float2(ehp[0]), e1 = __half22float2(ehp[1]);
    float2 e2 = __half22float2(ehp[2]), e3 = __half22float2(ehp[3]);

    float4 q0 = qr[0], q1 = qr[1], k0 = kr[0], k1 = kr[1];
    float p = 0.f;
    p = fmaf(q0.x, k0.x + e0.x, p);
    p = fmaf(q0.y, k0.y + e0.y, p);
    p = fmaf(q0.z, k0.z + e1.x, p);
    p = fmaf(q0.w, k0.w + e1.y, p);
    p = fmaf(q1.x, k1.x + e2.x, p);
    p = fmaf(q1.y, k1.y + e2.y, p);
    p = fmaf(q1.z, k1.z + e3.x, p);
    p = fmaf(q1.w, k1.w + e3.y, p);
    p += __shfl_xor_sync(0xffffffffu, p, 1);
    p += __shfl_xor_sync(0xffffffffu, p, 2);

    float a = p * (1.0f / xdist[w]) * RSQRT_DH;
    float ex = __expf(a);            // no max shift: cancels in the ratio
    if ((lane & 3) == 0) atomicAdd(&g_denom[dst * HEADS + h], ex);

    float4 v0 = vr[0], v1 = vr[1];
    float* op = g_out + (size_t)dst * DIM + lane * 8;
    float4 r0 = make_float4((v0.x + e0.x) * ex, (v0.y + e0.y) * ex,
                            (v0.z + e1.x) * ex, (v0.w + e1.y) * ex);
    float4 r1 = make_float4((v1.x + e2.x) * ex, (v1.y + e2.y) * ex,
                            (v1.z + e3.x) * ex, (v1.w + e3.y) * ex);
    red_add_v4(op, r0);
    red_add_v4(op + 4, r1);
}

// ---------------- LN1 residual: x + skip + msg/denom, + DP reduction -----------
__global__ __launch_bounds__(256) void resred_attn(
    const float* __restrict__ x, float* __restrict__ y, double* __restrict__ red)
{
    int i = blockIdx.x * blockDim.x + threadIdx.x;
    int i4 = i * 4;
    int row = i4 >> 8, c = i4 & 255, h = c >> 5;
    float4 xv = ((const float4*)x)[i];
    float4 sk = *(const float4*)(g_qkvs + (size_t)row * 1024 + 768 + c);
    float4 mg = ((const float4*)g_out)[i];
    float inv = 1.0f / (g_denom[row * HEADS + h] + 1e-16f);
    float4 s = make_float4(xv.x + sk.x + mg.x * inv, xv.y + sk.y + mg.y * inv,
                           xv.z + sk.z + mg.z * inv, xv.w + sk.w + mg.w * inv);
    ((float4*)y)[i] = s;

    double ls = (double)s.x + (double)s.y + (double)s.z + (double)s.w;
    double lq = (double)s.x * s.x + (double)s.y * s.y +
                (double)s.z * s.z + (double)s.w * s.w;
#pragma unroll
    for (int o = 16; o > 0; o >>= 1) {
        ls += __shfl_down_sync(0xffffffffu, ls, o);
        lq += __shfl_down_sync(0xffffffffu, lq, o);
    }
    __shared__ double shs[8], shq[8];
    int wid = threadIdx.x >> 5, lane = threadIdx.x & 31;
    if (lane == 0) { shs[wid] = ls; shq[wid] = lq; }
    __syncthreads();
    if (threadIdx.x == 0) {
        double ts = 0, tq = 0;
#pragma unroll
        for (int k = 0; k < 8; k++) { ts += shs[k]; tq += shq[k]; }
        atomicAdd(&red[0], ts);
        atomicAdd(&red[1], tq);
    }
}

// ---------------- plain residual + DP reduction --------------------------------
__global__ __launch_bounds__(256) void resred(
    const float* __restrict__ a, const float* __restrict__ b,
    float* __restrict__ y, double* __restrict__ red)
{
    int i = blockIdx.x * blockDim.x + threadIdx.x;
    float4 av = ((const float4*)a)[i];
    float4 bv = ((const float4*)b)[i];
    float4 s = make_float4(av.x + bv.x, av.y + bv.y, av.z + bv.z, av.w + bv.w);
    ((float4*)y)[i] = s;

    double ls = (double)s.x + (double)s.y + (double)s.z + (double)s.w;
    double lq = (double)s.x * s.x + (double)s.y * s.y +
                (double)s.z * s.z + (double)s.w * s.w;
#pragma unroll
    for (int o = 16; o > 0; o >>= 1) {
        ls += __shfl_down_sync(0xffffffffu, ls, o);
        lq += __shfl_down_sync(0xffffffffu, lq, o);
    }
    __shared__ double shs[8], shq[8];
    int wid = threadIdx.x >> 5, lane = threadIdx.x & 31;
    if (lane == 0) { shs[wid] = ls; shq[wid] = lq; }
    __syncthreads();
    if (threadIdx.x == 0) {
        double ts = 0, tq = 0;
#pragma unroll
        for (int k = 0; k < 8; k++) { ts += shs[k]; tq += shq[k]; }
        atomicAdd(&red[0], ts);
        atomicAdd(&red[1], tq);
    }
}

// ---------------- graph layernorm apply + 3-cat fp16 emit ----------------------
__global__ __launch_bounds__(256) void lnapply(
    const float* __restrict__ y, const float* __restrict__ g,
    const float* __restrict__ b, float* __restrict__ o,
    __half* __restrict__ ocat, const double* __restrict__ red)
{
    int i = blockIdx.x * blockDim.x + threadIdx.x;
    double mean = red[0] / (double)LN_CNT;
    double var  = red[1] / (double)LN_CNT - mean * mean;
    if (var < 0) var = 0;
    float inv = 1.0f / ((float)sqrt(var) + LN_EPS);
    float mu = (float)mean;

    int i4 = i * 4;
    int c = i4 % DIM;
    int row = i4 / DIM;
    float4 yv = ((const float4*)y)[i];
    float4 gv = *(const float4*)(g + c);
    float4 bv = *(const float4*)(b + c);
    float4 r;
    r.x = (yv.x - mu) * inv * gv.x + bv.x;
    r.y = (yv.y - mu) * inv * gv.y + bv.y;
    r.z = (yv.z - mu) * inv * gv.z + bv.z;
    r.w = (yv.w - mu) * inv * gv.w + bv.w;
    ((float4*)o)[i] = r;

    float vv[4] = {r.x, r.y, r.z, r.w};
    __half h[4], l[4];
#pragma unroll
    for (int j = 0; j < 4; j++) {
        h[j] = __float2half_rn(vv[j]);
        l[j] = __float2half_rn(vv[j] - __half2float(h[j]));
    }
    size_t base = (size_t)row * 3 * DIM + c;
    uint2 uh = make_uint2(pack_h2(h[0], h[1]), pack_h2(h[2], h[3]));
    uint2 ul = make_uint2(pack_h2(l[0], l[1]), pack_h2(l[2], l[3]));
    *(uint2*)(ocat + base) = uh;
    *(uint2*)(ocat + base + DIM) = ul;
    *(uint2*)(ocat + base + 2 * DIM) = uh;
}

// ---------------- host orchestration -------------------------------------------
extern "C" void kernel_launch(void* const* d_in, const int* in_sizes, int n_in,
                              void* d_out, int out_size)
{
    const float* x_in   = (const float*)d_in[0];
    const int*   ei     = (const int*)d_in[1];
    const float* x_edge = (const float*)d_in[2];
    const float* x_dist = (const float*)d_in[3];
    const float* Wq_a   = (const float*)d_in[4];
    const float* bq_a   = (const float*)d_in[5];
    const float* Wk_a   = (const float*)d_in[6];
    const float* bk_a   = (const float*)d_in[7];
    const float* Wv_a   = (const float*)d_in[8];
    const float* bv_a   = (const float*)d_in[9];
    const float* We_a   = (const float*)d_in[10];
    const float* Ws_a   = (const float*)d_in[11];
    const float* bs_a   = (const float*)d_in[12];
    const float* g1_a   = (const float*)d_in[13];
    const float* b1_a   = (const float*)d_in[14];
    const float* W1_a   = (const float*)d_in[15];
    const float* c1_a   = (const float*)d_in[16];
    const float* W2_a   = (const float*)d_in[17];
    const float* c2_a   = (const float*)d_in[18];
    const float* g2_a   = (const float*)d_in[19];
    const float* b2_a   = (const float*)d_in[20];

    static int smem_set = 0;
    if (!smem_set) {
        cudaFuncSetAttribute(gemm_mma, cudaFuncAttributeMaxDynamicSharedMemorySize,
                             NG_SMEM);
        cudaFuncSetAttribute(gemm_edge, cudaFuncAttributeMaxDynamicSharedMemorySize,
                             EG_SMEM);
        smem_set = 1;
    }

    float *qkvs_, *out_, *y_, *x_, *bqkvs_;
    double* red_;
    __half *eh3_, *xeh_, *xc_, *yc_, *hc_, *wt_;
    cudaGetSymbolAddress((void**)&qkvs_, g_qkvs);
    cudaGetSymbolAddress((void**)&eh3_,  g_e_h3);
    cudaGetSymbolAddress((void**)&out_,  g_out);
    cudaGetSymbolAddress((void**)&y_,    g_y);
    cudaGetSymbolAddress((void**)&x_,    g_x);
    cudaGetSymbolAddress((void**)&red_,  g_red);
    cudaGetSymbolAddress((void**)&bqkvs_, g_bqkvs);
    cudaGetSymbolAddress((void**)&xeh_,  g_xe_h);
    cudaGetSymbolAddress((void**)&xc_,   g_x_cat);
    cudaGetSymbolAddress((void**)&yc_,   g_y_cat);
    cudaGetSymbolAddress((void**)&hc_,   g_h_cat);
    cudaGetSymbolAddress((void**)&wt_,   g_wt_cat);

    const int elem4 = LN_CNT / 4;

    // one-time conversions
    cvt_cat3<<<(elem4 + 255) / 256, 256>>>(x_in, xc_, DIM, elem4);
    {
        int n4 = N_EDGES * DIM / 4;
        cvt_h<<<(n4 + 255) / 256, 256>>>(x_edge, xeh_, n4);
    }
    pack_bias<<<3, 1024>>>(bq_a, bk_a, bv_a, bs_a);
    dim3 tb(32, 8);
    for (int b = 0; b < 3; b++) {
        size_t wb = (size_t)b * WB;
        __half* wq = wt_ + wb + OW_QKVS;
        tconv<<<dim3(8, 8),  tb>>>(Wq_a + (size_t)b * DIM * DIM, wq,             DIM, DIM, 3);
        tconv<<<dim3(8, 8),  tb>>>(Wk_a + (size_t)b * DIM * DIM, wq + 256 * 768, DIM, DIM, 3);
        tconv<<<dim3(8, 8),  tb>>>(Wv_a + (size_t)b * DIM * DIM, wq + 512 * 768, DIM, DIM, 3);
        tconv<<<dim3(8, 8),  tb>>>(Ws_a + (size_t)b * DIM * DIM, wq + 768 * 768, DIM, DIM, 3);
        tconv<<<dim3(8, 8),  tb>>>(We_a + (size_t)b * DIM * DIM, wt_ + wb + OW_E, DIM, DIM, 1);
        tconv<<<dim3(32, 8), tb>>>(W1_a + (size_t)b * DIM * HID, wt_ + wb + OW_1, DIM, HID, 3);
        tconv<<<dim3(8, 32), tb>>>(W2_a + (size_t)b * HID * DIM, wt_ + wb + OW_2, HID, DIM, 3);
    }

    // edge projections for ALL blocks (A-resident, 1-cat fp16)
    gemm_edge<<<N_EDGES / 128, 128, EG_SMEM>>>(xeh_, wt_, eh3_);

    const float* xcur = x_in;
    for (int blk = 0; blk < 3; blk++) {
        size_t wb = (size_t)blk * WB;
        const float* g1 = g1_a + blk * DIM;
        const float* b1 = b1_a + blk * DIM;
        const float* c1 = c1_a + blk * HID;
        const float* c2 = c2_a + blk * DIM;
        const float* g2 = g2_a + blk * DIM;
        const float* b2 = b2_a + blk * DIM;

        init_kernel<<<(elem4 + 255) / 256, 256>>>();

        // fused Q|K|V|S projection
        gemm_mma<<<dim3(8, 125), 128, NG_SMEM>>>(
            xc_, wt_ + wb + OW_QKVS, bqkvs_ + blk * 1024,
            qkvs_, nullptr, N_NODES, 1024, 768, 0);

        // fused single-pass attention
        edge_attn<<<N_EDGES / 8, 256>>>(ei, x_dist,
                                        eh3_ + (size_t)blk * N_EDGES * DIM);

        // residual + graph LN 1
        resred_attn<<<elem4 / 256, 256>>>(xcur, y_, red_ + 0);
        lnapply<<<elem4 / 256, 256>>>(y_, g1, b1, y_, yc_, red_ + 0);

        // FFN (FFN1 emits 3-cat hidden directly)
        gemm_mma<<<dim3(8, 125), 128, NG_SMEM>>>(
            yc_, wt_ + wb + OW_1, c1, nullptr, hc_, N_NODES, HID, 768, 1);
        gemm_mma<<<dim3(2, 125), 128, NG_SMEM>>>(
            hc_, wt_ + wb + OW_2, c2, out_, nullptr, N_NODES, DIM, 3072, 0);

        // residual + graph LN 2
        resred<<<elem4 / 256, 256>>>(y_, out_, out_, red_ + 2);
        float* xdst = (blk == 2) ? (float*)d_out : x_;
        lnapply<<<elem4 / 256, 256>>>(out_, g2, b2, xdst, xc_, red_ + 2);

        xcur = x_;
    }
}

// round 8
// speedup vs baseline: 2.7461x; 1.0287x over previous
#include <cuda_runtime.h>
#include <cuda_fp16.h>
#include <math.h>
#include <stdint.h>

#define N_NODES 16000
#define N_EDGES 256000
#define DIM 256
#define HEADS 8
#define HID 1024
#define LN_CNT (N_NODES * DIM)
#define LN_EPS 1e-5f
#define RSQRT_DH 0.17677669529663687f

#define OW_QKVS 0              // [1024, 768]  3-cat
#define OW_E    786432         // [256, 256]   plain fp16
#define OW_1    851968         // [1024, 768]  3-cat
#define OW_2    1638400        // [256, 3072]  3-cat
#define WB      2424832

// ---------------- scratch -----------------------------------------------------
__device__ float    g_qkvs[(size_t)N_NODES * 1024];
__device__ __half   g_e_h3[3 * (size_t)N_EDGES * DIM];
__device__ float    g_out[N_NODES * DIM];
__device__ float    g_y[N_NODES * DIM];
__device__ float    g_x[N_NODES * DIM];
__device__ double   g_red[4];
__device__ float    g_bqkvs[3 * 1024];
__device__ __half   g_xe_h[(size_t)N_EDGES * DIM];
__device__ __half   g_x_cat[(size_t)N_NODES * 3 * DIM];
__device__ __half   g_y_cat[(size_t)N_NODES * 3 * DIM];
__device__ __half   g_h_cat[(size_t)N_NODES * 3 * HID];
__device__ __half   g_wt_cat[3 * WB];
// CSR
__device__ int      g_rowstart[N_NODES + 1];
__device__ int      g_cursor[N_NODES];
__device__ int      g_perm[N_EDGES];

// ---------------- helpers -----------------------------------------------------
__device__ __forceinline__ uint32_t smem_u32(const void* p) {
    uint32_t a;
    asm("{ .reg .u64 t; cvta.to.shared.u64 t, %1; cvt.u32.u64 %0, t; }"
        : "=r"(a) : "l"(p));
    return a;
}
__device__ __forceinline__ uint32_t pack_h2(__half a, __half b) {
    __half2 h2 = __halves2half2(a, b);
    return *(uint32_t*)&h2;
}
__device__ __forceinline__ void cp16(uint32_t dst, const void* src) {
    asm volatile("cp.async.cg.shared.global [%0], [%1], 16;"
                 :: "r"(dst), "l"(src) : "memory");
}
__device__ __forceinline__ void ldsm_x4(uint32_t* r, uint32_t addr) {
    asm volatile("ldmatrix.sync.aligned.m8n8.x4.shared.b16 {%0,%1,%2,%3}, [%4];"
                 : "=r"(r[0]), "=r"(r[1]), "=r"(r[2]), "=r"(r[3]) : "r"(addr));
}
__device__ __forceinline__ void mma16816(float* c, const uint32_t* a, uint32_t b0, uint32_t b1) {
    asm volatile(
        "mma.sync.aligned.m16n8k16.row.col.f32.f16.f16.f32 "
        "{%0,%1,%2,%3}, {%4,%5,%6,%7}, {%8,%9}, {%0,%1,%2,%3};"
        : "+f"(c[0]), "+f"(c[1]), "+f"(c[2]), "+f"(c[3])
        : "r"(a[0]), "r"(a[1]), "r"(a[2]), "r"(a[3]), "r"(b0), "r"(b1));
}

// ================== node GEMM 128x128 (4 warps, 3-stage) ======================
#define NG_SMEM 98304

__device__ __forceinline__ void load_chunk_n(
    uint32_t st, const __half* __restrict__ A, const __half* __restrict__ B,
    size_t rowA0, size_t rowB0, int K3, int k0, int tid)
{
#pragma unroll
    for (int i = 0; i < 8; i++) {
        int u = tid + (i << 7);
        int row = u >> 3, kk = u & 7;
        uint32_t off = (uint32_t)(row * 128 + kk * 16);
        uint32_t sw = off ^ ((off >> 3) & 0x70);
        cp16(st + sw, A + (rowA0 + row) * (size_t)K3 + k0 + kk * 8);
        cp16(st + 16384 + sw, B + (rowB0 + row) * (size_t)K3 + k0 + kk * 8);
    }
}

__global__ __launch_bounds__(128) void gemm_mma(
    const __half* __restrict__ A, const __half* __restrict__ B,
    const float* __restrict__ bias,
    float* __restrict__ Cf, __half* __restrict__ Ccat,
    int M, int N, int K3, int relu)
{
    extern __shared__ __align__(128) char smem[];
    uint32_t sbase = smem_u32(smem);

    int tid = threadIdx.x, lane = tid & 31, wid = tid >> 5;
    int warpM = wid >> 1, warpN = wid & 1;
    int tN = blockIdx.x, tM = blockIdx.y;
    size_t rowA0 = (size_t)tM * 128;
    size_t rowB0 = (size_t)tN * 128;
    int nch = K3 >> 6;

    float acc[4][8][4];
#pragma unroll
    for (int i = 0; i < 4; i++)
#pragma unroll
        for (int j = 0; j < 8; j++)
#pragma unroll
            for (int t = 0; t < 4; t++) acc[i][j][t] = 0.f;

    load_chunk_n(sbase, A, B, rowA0, rowB0, K3, 0, tid);
    asm volatile("cp.async.commit_group;" ::: "memory");
    load_chunk_n(sbase + 32768, A, B, rowA0, rowB0, K3, 64, tid);
    asm volatile("cp.async.commit_group;" ::: "memory");

    for (int c = 0; c < nch; c++) {
        if (c + 2 < nch) {
            uint32_t sb = sbase + (uint32_t)((c + 2) % 3) * 32768u;
            load_chunk_n(sb, A, B, rowA0, rowB0, K3, (c + 2) << 6, tid);
            asm volatile("cp.async.commit_group;" ::: "memory");
            asm volatile("cp.async.wait_group 2;" ::: "memory");
        } else if (c + 1 < nch) {
            asm volatile("cp.async.wait_group 1;" ::: "memory");
        } else {
            asm volatile("cp.async.wait_group 0;" ::: "memory");
        }
        __syncthreads();

        uint32_t aB = sbase + (uint32_t)(c % 3) * 32768u;
        uint32_t bB = aB + 16384;
#pragma unroll
        for (int ks = 0; ks < 4; ks++) {
            uint32_t af[4][4], bf[4][4];
#pragma unroll
            for (int mf = 0; mf < 4; mf++) {
                int row = warpM * 64 + mf * 16 + (lane & 15);
                uint32_t off = (uint32_t)(row * 128 + ks * 32 + ((lane >> 4) << 4));
                off ^= (off >> 3) & 0x70;
                ldsm_x4(af[mf], aB + off);
            }
#pragma unroll
            for (int nf2 = 0; nf2 < 4; nf2++) {
                int row = warpN * 64 + nf2 * 16 + (lane & 15);
                uint32_t off = (uint32_t)(row * 128 + ks * 32 + ((lane >> 4) << 4));
                off ^= (off >> 3) & 0x70;
                ldsm_x4(bf[nf2], bB + off);
            }
#pragma unroll
            for (int mf = 0; mf < 4; mf++)
#pragma unroll
                for (int nf2 = 0; nf2 < 4; nf2++) {
                    mma16816(acc[mf][nf2 * 2],     af[mf], bf[nf2][0], bf[nf2][2]);
                    mma16816(acc[mf][nf2 * 2 + 1], af[mf], bf[nf2][1], bf[nf2][3]);
                }
        }
        __syncthreads();
    }

    int m0 = tM * 128 + warpM * 64;
    int n0 = tN * 128 + warpN * 64;
#pragma unroll
    for (int mf = 0; mf < 4; mf++) {
#pragma unroll
        for (int nf = 0; nf < 8; nf++) {
            int r = m0 + mf * 16 + (lane >> 2);
            int col = n0 + nf * 8 + ((lane & 3) << 1);
            float b0 = bias ? __ldg(bias + col) : 0.f;
            float b1 = bias ? __ldg(bias + col + 1) : 0.f;
            float v00 = acc[mf][nf][0] + b0, v01 = acc[mf][nf][1] + b1;
            float v10 = acc[mf][nf][2] + b0, v11 = acc[mf][nf][3] + b1;
            if (relu) {
                v00 = fmaxf(v00, 0.f); v01 = fmaxf(v01, 0.f);
                v10 = fmaxf(v10, 0.f); v11 = fmaxf(v11, 0.f);
            }
            if (Cf) {
                *(float2*)(Cf + (size_t)r * N + col) = make_float2(v00, v01);
                *(float2*)(Cf + (size_t)(r + 8) * N + col) = make_float2(v10, v11);
            }
            if (Ccat) {
                __half h00 = __float2half_rn(v00), h01 = __float2half_rn(v01);
                __half h10 = __float2half_rn(v10), h11 = __float2half_rn(v11);
                uint32_t uh0 = pack_h2(h00, h01), uh1 = pack_h2(h10, h11);
                uint32_t ul0 = pack_h2(__float2half_rn(v00 - __half2float(h00)),
                                       __float2half_rn(v01 - __half2float(h01)));
                uint32_t ul1 = pack_h2(__float2half_rn(v10 - __half2float(h10)),
                                       __float2half_rn(v11 - __half2float(h11)));
                size_t b0a = (size_t)r * 3 * N + col;
                size_t b1a = (size_t)(r + 8) * 3 * N + col;
                *(uint32_t*)(Ccat + b0a) = uh0;
                *(uint32_t*)(Ccat + b0a + N) = ul0;
                *(uint32_t*)(Ccat + b0a + 2 * N) = uh0;
                *(uint32_t*)(Ccat + b1a) = uh1;
                *(uint32_t*)(Ccat + b1a + N) = ul1;
                *(uint32_t*)(Ccat + b1a + 2 * N) = uh1;
            }
        }
    }
}

// ================== node GEMM 128x256 (8 warps, 2-stage) — FFN2 ===============
#define NG2_SMEM 98304

__device__ __forceinline__ void load_chunk_n2(
    uint32_t st, const __half* __restrict__ A, const __half* __restrict__ B,
    size_t rowA0, size_t rowB0, int K3, int k0, int tid)
{
#pragma unroll
    for (int i = 0; i < 4; i++) {
        int u = tid + (i << 8);
        int row = u >> 3, kk = u & 7;
        uint32_t off = (uint32_t)(row * 128 + kk * 16);
        uint32_t sw = off ^ ((off >> 3) & 0x70);
        cp16(st + sw, A + (rowA0 + row) * (size_t)K3 + k0 + kk * 8);
    }
#pragma unroll
    for (int i = 0; i < 8; i++) {
        int u = tid + (i << 8);
        int row = u >> 3, kk = u & 7;
        uint32_t off = (uint32_t)(row * 128 + kk * 16);
        uint32_t sw = off ^ ((off >> 3) & 0x70);
        cp16(st + 16384 + sw, B + (rowB0 + row) * (size_t)K3 + k0 + kk * 8);
    }
}

__global__ __launch_bounds__(256) void gemm_mma2(
    const __half* __restrict__ A, const __half* __restrict__ B,
    const float* __restrict__ bias, float* __restrict__ Cf,
    int M, int N, int K3)
{
    extern __shared__ __align__(128) char smem[];
    uint32_t sbase = smem_u32(smem);

    int tid = threadIdx.x, lane = tid & 31, wid = tid >> 5;
    int warpM = wid >> 2, warpN = wid & 3;
    int tN = blockIdx.x, tM = blockIdx.y;
    size_t rowA0 = (size_t)tM * 128;
    size_t rowB0 = (size_t)tN * 256;
    int nch = K3 >> 6;

    float acc[4][8][4];
#pragma unroll
    for (int i = 0; i < 4; i++)
#pragma unroll
        for (int j = 0; j < 8; j++)
#pragma unroll
            for (int t = 0; t < 4; t++) acc[i][j][t] = 0.f;

    load_chunk_n2(sbase, A, B, rowA0, rowB0, K3, 0, tid);
    asm volatile("cp.async.commit_group;" ::: "memory");

    for (int c = 0; c < nch; c++) {
        if (c + 1 < nch) {
            uint32_t sb = sbase + (uint32_t)((c + 1) & 1) * 49152u;
            load_chunk_n2(sb, A, B, rowA0, rowB0, K3, (c + 1) << 6, tid);
            asm volatile("cp.async.commit_group;" ::: "memory");
            asm volatile("cp.async.wait_group 1;" ::: "memory");
        } else {
            asm volatile("cp.async.wait_group 0;" ::: "memory");
        }
        __syncthreads();

        uint32_t aB = sbase + (uint32_t)(c & 1) * 49152u;
        uint32_t bB = aB + 16384;
#pragma unroll
        for (int ks = 0; ks < 4; ks++) {
            uint32_t af[4][4], bf[4][4];
#pragma unroll
            for (int mf = 0; mf < 4; mf++) {
                int row = warpM * 64 + mf * 16 + (lane & 15);
                uint32_t off = (uint32_t)(row * 128 + ks * 32 + ((lane >> 4) << 4));
                off ^= (off >> 3) & 0x70;
                ldsm_x4(af[mf], aB + off);
            }
#pragma unroll
            for (int nf2 = 0; nf2 < 4; nf2++) {
                int row = warpN * 64 + nf2 * 16 + (lane & 15);
                uint32_t off = (uint32_t)(row * 128 + ks * 32 + ((lane >> 4) << 4));
                off ^= (off >> 3) & 0x70;
                ldsm_x4(bf[nf2], bB + off);
            }
#pragma unroll
            for (int mf = 0; mf < 4; mf++)
#pragma unroll
                for (int nf2 = 0; nf2 < 4; nf2++) {
                    mma16816(acc[mf][nf2 * 2],     af[mf], bf[nf2][0], bf[nf2][2]);
                    mma16816(acc[mf][nf2 * 2 + 1], af[mf], bf[nf2][1], bf[nf2][3]);
                }
        }
        __syncthreads();
    }

    int m0 = tM * 128 + warpM * 64;
    int n0 = tN * 256 + warpN * 64;
#pragma unroll
    for (int mf = 0; mf < 4; mf++) {
#pragma unroll
        for (int nf = 0; nf < 8; nf++) {
            int r = m0 + mf * 16 + (lane >> 2);
            int col = n0 + nf * 8 + ((lane & 3) << 1);
            float b0 = bias ? __ldg(bias + col) : 0.f;
            float b1 = bias ? __ldg(bias + col + 1) : 0.f;
            *(float2*)(Cf + (size_t)r * N + col) =
                make_float2(acc[mf][nf][0] + b0, acc[mf][nf][1] + b1);
            *(float2*)(Cf + (size_t)(r + 8) * N + col) =
                make_float2(acc[mf][nf][2] + b0, acc[mf][nf][3] + b1);
        }
    }
}

// ================== edge GEMM: A-resident, all 3 blocks =======================
#define EG_SMEM 98304

__global__ __launch_bounds__(128) void gemm_edge(
    const __half* __restrict__ XE, const __half* __restrict__ WT,
    __half* __restrict__ EH)
{
    extern __shared__ __align__(128) char smem[];
    uint32_t sbase = smem_u32(smem);
    uint32_t bbase = sbase + 65536;

    int tid = threadIdx.x, lane = tid & 31, wid = tid >> 5;
    int warpM = wid >> 1, warpN = wid & 1;
    size_t rowA0 = (size_t)blockIdx.x * 128;

#pragma unroll
    for (int ch = 0; ch < 4; ch++) {
#pragma unroll
        for (int i = 0; i < 8; i++) {
            int u = tid + (i << 7);
            int row = u >> 3, kk = u & 7;
            uint32_t off = (uint32_t)(row * 128 + kk * 16);
            uint32_t sw = off ^ ((off >> 3) & 0x70);
            cp16(sbase + ch * 16384 + sw, XE + (rowA0 + row) * 256 + ch * 64 + kk * 8);
        }
    }
    {
#pragma unroll
        for (int i = 0; i < 8; i++) {
            int u = tid + (i << 7);
            int row = u >> 3, kk = u & 7;
            uint32_t off = (uint32_t)(row * 128 + kk * 16);
            uint32_t sw = off ^ ((off >> 3) & 0x70);
            cp16(bbase + sw, WT + OW_E + (size_t)row * 256 + kk * 8);
        }
    }
    asm volatile("cp.async.commit_group;" ::: "memory");

    float acc[4][8][4];
#pragma unroll
    for (int i = 0; i < 4; i++)
#pragma unroll
        for (int j = 0; j < 8; j++)
#pragma unroll
            for (int t = 0; t < 4; t++) acc[i][j][t] = 0.f;

    for (int it = 0; it < 24; it++) {
        if (it < 23) {
            int j = it + 1;
            int wt = j >> 2, ck = j & 3;
            int blkj = wt >> 1, nh = wt & 1;
            const __half* Bp = WT + (size_t)blkj * WB + OW_E;
            uint32_t bb = bbase + (uint32_t)(j & 1) * 16384u;
#pragma unroll
            for (int i = 0; i < 8; i++) {
                int u = tid + (i << 7);
                int row = u >> 3, kk = u & 7;
                uint32_t off = (uint32_t)(row * 128 + kk * 16);
                uint32_t sw = off ^ ((off >> 3) & 0x70);
                cp16(bb + sw, Bp + (size_t)(nh * 128 + row) * 256 + ck * 64 + kk * 8);
            }
            asm volatile("cp.async.commit_group;" ::: "memory");
            asm volatile("cp.async.wait_group 1;" ::: "memory");
        } else {
            asm volatile("cp.async.wait_group 0;" ::: "memory");
        }
        __syncthreads();

        int ck = it & 3;
        uint32_t aB = sbase + (uint32_t)ck * 16384u;
        uint32_t bB = bbase + (uint32_t)(it & 1) * 16384u;
#pragma unroll
        for (int ks = 0; ks < 4; ks++) {
            uint32_t af[4][4], bf[4][4];
#pragma unroll
            for (int mf = 0; mf < 4; mf++) {
                int row = warpM * 64 + mf * 16 + (lane & 15);
                uint32_t off = (uint32_t)(row * 128 + ks * 32 + ((lane >> 4) << 4));
                off ^= (off >> 3) & 0x70;
                ldsm_x4(af[mf], aB + off);
            }
#pragma unroll
            for (int nf2 = 0; nf2 < 4; nf2++) {
                int row = warpN * 64 + nf2 * 16 + (lane & 15);
                uint32_t off = (uint32_t)(row * 128 + ks * 32 + ((lane >> 4) << 4));
                off ^= (off >> 3) & 0x70;
                ldsm_x4(bf[nf2], bB + off);
            }
#pragma unroll
            for (int mf = 0; mf < 4; mf++)
#pragma unroll
                for (int nf2 = 0; nf2 < 4; nf2++) {
                    mma16816(acc[mf][nf2 * 2],     af[mf], bf[nf2][0], bf[nf2][2]);
                    mma16816(acc[mf][nf2 * 2 + 1], af[mf], bf[nf2][1], bf[nf2][3]);
                }
        }
        __syncthreads();

        if (ck == 3) {
            int wt = it >> 2;
            int blk = wt >> 1, nh = wt & 1;
            __half* out = EH + (size_t)blk * N_EDGES * DIM;
#pragma unroll
            for (int mf = 0; mf < 4; mf++) {
#pragma unroll
                for (int nf = 0; nf < 8; nf++) {
                    int r = (int)rowA0 + warpM * 64 + mf * 16 + (lane >> 2);
                    int col = nh * 128 + warpN * 64 + nf * 8 + ((lane & 3) << 1);
                    *(__half2*)(out + (size_t)r * DIM + col) =
                        __floats2half2_rn(acc[mf][nf][0], acc[mf][nf][1]);
                    *(__half2*)(out + (size_t)(r + 8) * DIM + col) =
                        __floats2half2_rn(acc[mf][nf][2], acc[mf][nf][3]);
#pragma unroll
                    for (int t = 0; t < 4; t++) acc[mf][nf][t] = 0.f;
                }
            }
        }
    }
}

// ---------------- CSR build ----------------------------------------------------
__global__ void zero_deg() {
    int i = blockIdx.x * blockDim.x + threadIdx.x;
    if (i < N_NODES) g_cursor[i] = 0;
}
__global__ void hist_dst(const int* __restrict__ ei) {
    int i = blockIdx.x * blockDim.x + threadIdx.x;
    if (i < N_EDGES) atomicAdd(&g_cursor[ei[N_EDGES + i]], 1);
}
__global__ __launch_bounds__(1024) void scan16k() {
    __shared__ int warp_tot[32];
    int tid = threadIdx.x, lane = tid & 31, wid = tid >> 5;
    int base = tid * 16;
    int vals[16];
    int s = 0;
#pragma unroll
    for (int t = 0; t < 16; t++) {
        int idx = base + t;
        int v = (idx < N_NODES) ? g_cursor[idx] : 0;
        vals[t] = s;
        s += v;
    }
    int x = s;
#pragma unroll
    for (int o = 1; o < 32; o <<= 1) {
        int n = __shfl_up_sync(0xffffffffu, x, o);
        if (lane >= o) x += n;
    }
    if (lane == 31) warp_tot[wid] = x;
    __syncthreads();
    if (wid == 0) {
        int t = warp_tot[lane];
        int y = t;
#pragma unroll
        for (int o = 1; o < 32; o <<= 1) {
            int n = __shfl_up_sync(0xffffffffu, y, o);
            if (lane >= o) y += n;
        }
        warp_tot[lane] = y - t;   // exclusive
    }
    __syncthreads();
    int offset = warp_tot[wid] + (x - s);
#pragma unroll
    for (int t = 0; t < 16; t++) {
        int idx = base + t;
        if (idx < N_NODES) {
            int r = offset + vals[t];
            g_rowstart[idx] = r;
        }
    }
    if (tid == 1023) g_rowstart[N_NODES] = offset + s;
    __syncthreads();
#pragma unroll
    for (int t = 0; t < 16; t++) {
        int idx = base + t;
        if (idx < N_NODES) g_cursor[idx] = g_rowstart[idx];
    }
}
__global__ void scatter_perm(const int* __restrict__ ei) {
    int i = blockIdx.x * blockDim.x + threadIdx.x;
    if (i < N_EDGES) {
        int d = ei[N_EDGES + i];
        int pos = atomicAdd(&g_cursor[d], 1);
        g_perm[pos] = i;
    }
}

// ---------------- converters / weight prep -------------------------------------
__global__ __launch_bounds__(256) void cvt_cat3(
    const float* __restrict__ s, __half* __restrict__ d, int K, int n4)
{
    int i = blockIdx.x * blockDim.x + threadIdx.x;
    if (i >= n4) return;
    int i4 = i * 4;
    int row = i4 / K, col = i4 % K;
    float4 v = ((const float4*)s)[i];
    float vv[4] = {v.x, v.y, v.z, v.w};
    __half h[4], l[4];
#pragma unroll
    for (int j = 0; j < 4; j++) {
        h[j] = __float2half_rn(vv[j]);
        l[j] = __float2half_rn(vv[j] - __half2float(h[j]));
    }
    size_t base = (size_t)row * 3 * K + col;
    uint2 uh = make_uint2(pack_h2(h[0], h[1]), pack_h2(h[2], h[3]));
    uint2 ul = make_uint2(pack_h2(l[0], l[1]), pack_h2(l[2], l[3]));
    *(uint2*)(d + base) = uh;
    *(uint2*)(d + base + K) = ul;
    *(uint2*)(d + base + 2 * K) = uh;
}

__global__ __launch_bounds__(256) void cvt_h(
    const float* __restrict__ s, __half* __restrict__ d, int n4)
{
    int i = blockIdx.x * blockDim.x + threadIdx.x;
    if (i >= n4) return;
    float4 v = ((const float4*)s)[i];
    *(uint2*)(d + (size_t)i * 4) =
        make_uint2(pack_h2(__float2half_rn(v.x), __float2half_rn(v.y)),
                   pack_h2(__float2half_rn(v.z), __float2half_rn(v.w)));
}

__global__ void tconv(const float* __restrict__ W, __half* __restrict__ out,
                      int K, int N, int cat)
{
    __shared__ float t[32][33];
    int tx = threadIdx.x, ty = threadIdx.y;
    int n0 = blockIdx.x * 32, k0 = blockIdx.y * 32;
#pragma unroll
    for (int r = 0; r < 4; r++)
        t[ty + 8 * r][tx] = W[(size_t)(k0 + ty + 8 * r) * N + n0 + tx];
    __syncthreads();
    int stride = cat * K;
#pragma unroll
    for (int r = 0; r < 4; r++) {
        int nl = ty + 8 * r;
        float v = t[tx][nl];
        size_t o = (size_t)(n0 + nl) * stride + k0 + tx;
        __half h = __float2half_rn(v);
        out[o] = h;
        if (cat == 3) {
            out[o + K] = h;
            out[o + 2 * K] = __float2half_rn(v - __half2float(h));
        }
    }
}

__global__ void pack_bias(const float* __restrict__ bq, const float* __restrict__ bk,
                          const float* __restrict__ bv, const float* __restrict__ bs)
{
    int b = blockIdx.x, t = threadIdx.x;
    float v = (t < 256) ? bq[b * 256 + t]
            : (t < 512) ? bk[b * 256 + t - 256]
            : (t < 768) ? bv[b * 256 + t - 512]
                        : bs[b * 256 + t - 768];
    g_bqkvs[b * 1024 + t] = v;
}

__global__ void zero_red() {
    if (threadIdx.x < 4) g_red[threadIdx.x] = 0.0;
}

// ---------------- fused CSR attention + skip + residual + LN reduction ---------
// one warp per destination node; 8 warps per CTA
__global__ __launch_bounds__(256) void attn_csr(
    const int* __restrict__ ei, const float* __restrict__ xdist,
    const __half* __restrict__ eh, const float* __restrict__ x,
    float* __restrict__ y, double* __restrict__ red)
{
    int tid = threadIdx.x, lane = tid & 31, wid = tid >> 5;
    int node = blockIdx.x * 8 + wid;

    double ls = 0.0, lq = 0.0;
    if (node < N_NODES) {
        const float* qrow = g_qkvs + (size_t)node * 1024;
        float4 q0 = *(const float4*)(qrow + lane * 8);
        float4 q1 = *(const float4*)(qrow + lane * 8 + 4);

        int start = g_rowstart[node];
        int end   = g_rowstart[node + 1];

        float m0 = 0.f, m1 = 0.f, m2 = 0.f, m3 = 0.f;
        float m4 = 0.f, m5 = 0.f, m6 = 0.f, m7 = 0.f;
        float denom = 0.f;

        for (int j = start; j < end; j++) {
            int eidx = g_perm[j];
            int src = ei[eidx];
            float invd = 1.0f / xdist[eidx];

            const float* krow = g_qkvs + (size_t)src * 1024 + 256;
            const float* vrow = g_qkvs + (size_t)src * 1024 + 512;
            float4 k0 = *(const float4*)(krow + lane * 8);
            float4 k1 = *(const float4*)(krow + lane * 8 + 4);
            int4 evi = *(const int4*)(eh + (size_t)eidx * DIM + lane * 8);
            __half2* ehp = (__half2*)&evi;
            float2 e0 = __half22float2(ehp[0]), e1 = __half22float2(ehp[1]);
            float2 e2 = __half22float2(ehp[2]), e3 = __half22float2(ehp[3]);

            float p = 0.f;
            p = fmaf(q0.x, k0.x + e0.x, p);
            p = fmaf(q0.y, k0.y + e0.y, p);
            p = fmaf(q0.z, k0.z + e1.x, p);
            p = fmaf(q0.w, k0.w + e1.y, p);
            p = fmaf(q1.x, k1.x + e2.x, p);
            p = fmaf(q1.y, k1.y + e2.y, p);
            p = fmaf(q1.z, k1.z + e3.x, p);
            p = fmaf(q1.w, k1.w + e3.y, p);
            p += __shfl_xor_sync(0xffffffffu, p, 1);
            p += __shfl_xor_sync(0xffffffffu, p, 2);

            float ex = __expf(p * invd * RSQRT_DH);
            denom += ex;

            float4 v0 = *(const float4*)(vrow + lane * 8);
            float4 v1 = *(const float4*)(vrow + lane * 8 + 4);
            m0 = fmaf(v0.x + e0.x, ex, m0);
            m1 = fmaf(v0.y + e0.y, ex, m1);
            m2 = fmaf(v0.z + e1.x, ex, m2);
            m3 = fmaf(v0.w + e1.y, ex, m3);
            m4 = fmaf(v1.x + e2.x, ex, m4);
            m5 = fmaf(v1.y + e2.y, ex, m5);
            m6 = fmaf(v1.z + e3.x, ex, m6);
            m7 = fmaf(v1.w + e3.y, ex, m7);
        }

        float inv = 1.0f / (denom + 1e-16f);
        const float* xr = x + (size_t)node * 256 + lane * 8;
        const float* sk = g_qkvs + (size_t)node * 1024 + 768 + lane * 8;
        float4 xv0 = *(const float4*)(xr);
        float4 xv1 = *(const float4*)(xr + 4);
        float4 sk0 = *(const float4*)(sk);
        float4 sk1 = *(const float4*)(sk + 4);

        float r0 = xv0.x + sk0.x + m0 * inv;
        float r1 = xv0.y + sk0.y + m1 * inv;
        float r2 = xv0.z + sk0.z + m2 * inv;
        float r3 = xv0.w + sk0.w + m3 * inv;
        float r4 = xv1.x + sk1.x + m4 * inv;
        float r5 = xv1.y + sk1.y + m5 * inv;
        float r6 = xv1.z + sk1.z + m6 * inv;
        float r7 = xv1.w + sk1.w + m7 * inv;

        float* yp = y + (size_t)node * 256 + lane * 8;
        *(float4*)(yp)     = make_float4(r0, r1, r2, r3);
        *(float4*)(yp + 4) = make_float4(r4, r5, r6, r7);

        ls = (double)r0 + (double)r1 + (double)r2 + (double)r3 +
             (double)r4 + (double)r5 + (double)r6 + (double)r7;
        lq = (double)r0 * r0 + (double)r1 * r1 + (double)r2 * r2 + (double)r3 * r3 +
             (double)r4 * r4 + (double)r5 * r5 + (double)r6 * r6 + (double)r7 * r7;
    }

#pragma unroll
    for (int o = 16; o > 0; o >>= 1) {
        ls += __shfl_down_sync(0xffffffffu, ls, o);
        lq += __shfl_down_sync(0xffffffffu, lq, o);
    }
    __shared__ double shs[8], shq[8];
    if (lane == 0) { shs[wid] = ls; shq[wid] = lq; }
    __syncthreads();
    if (tid == 0) {
        double ts = 0, tq = 0;
#pragma unroll
        for (int k = 0; k < 8; k++) { ts += shs[k]; tq += shq[k]; }
        atomicAdd(&red[0], ts);
        atomicAdd(&red[1], tq);
    }
}

// ---------------- plain residual + DP reduction --------------------------------
__global__ __launch_bounds__(256) void resred(
    const float* __restrict__ a, const float* __restrict__ b,
    float* __restrict__ y, double* __restrict__ red)
{
    int i = blockIdx.x * blockDim.x + threadIdx.x;
    float4 av = ((const float4*)a)[i];
    float4 bv = ((const float4*)b)[i];
    float4 s = make_float4(av.x + bv.x, av.y + bv.y, av.z + bv.z, av.w + bv.w);
    ((float4*)y)[i] = s;

    double ls = (double)s.x + (double)s.y + (double)s.z + (double)s.w;
    double lq = (double)s.x * s.x + (double)s.y * s.y +
                (double)s.z * s.z + (double)s.w * s.w;
#pragma unroll
    for (int o = 16; o > 0; o >>= 1) {
        ls += __shfl_down_sync(0xffffffffu, ls, o);
        lq += __shfl_down_sync(0xffffffffu, lq, o);
    }
    __shared__ double shs[8], shq[8];
    int wid = threadIdx.x >> 5, lane = threadIdx.x & 31;
    if (lane == 0) { shs[wid] = ls; shq[wid] = lq; }
    __syncthreads();
    if (threadIdx.x == 0) {
        double ts = 0, tq = 0;
#pragma unroll
        for (int k = 0; k < 8; k++) { ts += shs[k]; tq += shq[k]; }
        atomicAdd(&red[0], ts);
        atomicAdd(&red[1], tq);
    }
}

// ---------------- graph layernorm apply + 3-cat fp16 emit ----------------------
__global__ __launch_bounds__(256) void lnapply(
    const float* __restrict__ y, const float* __restrict__ g,
    const float* __restrict__ b, float* __restrict__ o,
    __half* __restrict__ ocat, const double* __restrict__ red)
{
    int i = blockIdx.x * blockDim.x + threadIdx.x;
    double mean = red[0] / (double)LN_CNT;
    double var  = red[1] / (double)LN_CNT - mean * mean;
    if (var < 0) var = 0;
    float inv = 1.0f / ((float)sqrt(var) + LN_EPS);
    float mu = (float)mean;

    int i4 = i * 4;
    int c = i4 % DIM;
    int row = i4 / DIM;
    float4 yv = ((const float4*)y)[i];
    float4 gv = *(const float4*)(g + c);
    float4 bv = *(const float4*)(b + c);
    float4 r;
    r.x = (yv.x - mu) * inv * gv.x + bv.x;
    r.y = (yv.y - mu) * inv * gv.y + bv.y;
    r.z = (yv.z - mu) * inv * gv.z + bv.z;
    r.w = (yv.w - mu) * inv * gv.w + bv.w;
    ((float4*)o)[i] = r;

    float vv[4] = {r.x, r.y, r.z, r.w};
    __half h[4], l[4];
#pragma unroll
    for (int j = 0; j < 4; j++) {
        h[j] = __float2half_rn(vv[j]);
        l[j] = __float2half_rn(vv[j] - __half2float(h[j]));
    }
    size_t base = (size_t)row * 3 * DIM + c;
    uint2 uh = make_uint2(pack_h2(h[0], h[1]), pack_h2(h[2], h[3]));
    uint2 ul = make_uint2(pack_h2(l[0], l[1]), pack_h2(l[2], l[3]));
    *(uint2*)(ocat + base) = uh;
    *(uint2*)(ocat + base + DIM) = ul;
    *(uint2*)(ocat + base + 2 * DIM) = uh;
}

// ---------------- host orchestration -------------------------------------------
extern "C" void kernel_launch(void* const* d_in, const int* in_sizes, int n_in,
                              void* d_out, int out_size)
{
    const float* x_in   = (const float*)d_in[0];
    const int*   ei     = (const int*)d_in[1];
    const float* x_edge = (const float*)d_in[2];
    const float* x_dist = (const float*)d_in[3];
    const float* Wq_a   = (const float*)d_in[4];
    const float* bq_a   = (const float*)d_in[5];
    const float* Wk_a   = (const float*)d_in[6];
    const float* bk_a   = (const float*)d_in[7];
    const float* Wv_a   = (const float*)d_in[8];
    const float* bv_a   = (const float*)d_in[9];
    const float* We_a   = (const float*)d_in[10];
    const float* Ws_a   = (const float*)d_in[11];
    const float* bs_a   = (const float*)d_in[12];
    const float* g1_a   = (const float*)d_in[13];
    const float* b1_a   = (const float*)d_in[14];
    const float* W1_a   = (const float*)d_in[15];
    const float* c1_a   = (const float*)d_in[16];
    const float* W2_a   = (const float*)d_in[17];
    const float* c2_a   = (const float*)d_in[18];
    const float* g2_a   = (const float*)d_in[19];
    const float* b2_a   = (const float*)d_in[20];

    static int smem_set = 0;
    if (!smem_set) {
        cudaFuncSetAttribute(gemm_mma, cudaFuncAttributeMaxDynamicSharedMemorySize, NG_SMEM);
        cudaFuncSetAttribute(gemm_mma2, cudaFuncAttributeMaxDynamicSharedMemorySize, NG2_SMEM);
        cudaFuncSetAttribute(gemm_edge, cudaFuncAttributeMaxDynamicSharedMemorySize, EG_SMEM);
        smem_set = 1;
    }

    float *qkvs_, *out_, *y_, *x_, *bqkvs_;
    double* red_;
    __half *eh3_, *xeh_, *xc_, *yc_, *hc_, *wt_;
    cudaGetSymbolAddress((void**)&qkvs_, g_qkvs);
    cudaGetSymbolAddress((void**)&eh3_,  g_e_h3);
    cudaGetSymbolAddress((void**)&out_,  g_out);
    cudaGetSymbolAddress((void**)&y_,    g_y);
    cudaGetSymbolAddress((void**)&x_,    g_x);
    cudaGetSymbolAddress((void**)&red_,  g_red);
    cudaGetSymbolAddress((void**)&bqkvs_, g_bqkvs);
    cudaGetSymbolAddress((void**)&xeh_,  g_xe_h);
    cudaGetSymbolAddress((void**)&xc_,   g_x_cat);
    cudaGetSymbolAddress((void**)&yc_,   g_y_cat);
    cudaGetSymbolAddress((void**)&hc_,   g_h_cat);
    cudaGetSymbolAddress((void**)&wt_,   g_wt_cat);

    const int elem4 = LN_CNT / 4;

    // one-time: conversions, weight prep, CSR build, edge projections
    cvt_cat3<<<(elem4 + 255) / 256, 256>>>(x_in, xc_, DIM, elem4);
    {
        int n4 = N_EDGES * DIM / 4;
        cvt_h<<<(n4 + 255) / 256, 256>>>(x_edge, xeh_, n4);
    }
    pack_bias<<<3, 1024>>>(bq_a, bk_a, bv_a, bs_a);
    dim3 tb(32, 8);
    for (int b = 0; b < 3; b++) {
        size_t wb = (size_t)b * WB;
        __half* wq = wt_ + wb + OW_QKVS;
        tconv<<<dim3(8, 8),  tb>>>(Wq_a + (size_t)b * DIM * DIM, wq,             DIM, DIM, 3);
        tconv<<<dim3(8, 8),  tb>>>(Wk_a + (size_t)b * DIM * DIM, wq + 256 * 768, DIM, DIM, 3);
        tconv<<<dim3(8, 8),  tb>>>(Wv_a + (size_t)b * DIM * DIM, wq + 512 * 768, DIM, DIM, 3);
        tconv<<<dim3(8, 8),  tb>>>(Ws_a + (size_t)b * DIM * DIM, wq + 768 * 768, DIM, DIM, 3);
        tconv<<<dim3(8, 8),  tb>>>(We_a + (size_t)b * DIM * DIM, wt_ + wb + OW_E, DIM, DIM, 1);
        tconv<<<dim3(32, 8), tb>>>(W1_a + (size_t)b * DIM * HID, wt_ + wb + OW_1, DIM, HID, 3);
        tconv<<<dim3(8, 32), tb>>>(W2_a + (size_t)b * HID * DIM, wt_ + wb + OW_2, HID, DIM, 3);
    }
    zero_deg<<<(N_NODES + 255) / 256, 256>>>();
    hist_dst<<<(N_EDGES + 255) / 256, 256>>>(ei);
    scan16k<<<1, 1024>>>();
    scatter_perm<<<(N_EDGES + 255) / 256, 256>>>(ei);

    gemm_edge<<<N_EDGES / 128, 128, EG_SMEM>>>(xeh_, wt_, eh3_);

    const float* xcur = x_in;
    for (int blk = 0; blk < 3; blk++) {
        size_t wb = (size_t)blk * WB;
        const float* g1 = g1_a + blk * DIM;
        const float* b1 = b1_a + blk * DIM;
        const float* c1 = c1_a + blk * HID;
        const float* c2 = c2_a + blk * DIM;
        const float* g2 = g2_a + blk * DIM;
        const float* b2 = b2_a + blk * DIM;

        zero_red<<<1, 32>>>();

        gemm_mma<<<dim3(8, 125), 128, NG_SMEM>>>(
            xc_, wt_ + wb + OW_QKVS, bqkvs_ + blk * 1024,
            qkvs_, nullptr, N_NODES, 1024, 768, 0);

        // fused attention + skip + residual + LN reduction (CSR, warp/node)
        attn_csr<<<N_NODES / 8, 256>>>(ei, x_dist,
                                       eh3_ + (size_t)blk * N_EDGES * DIM,
                                       xcur, y_, red_ + 0);
        lnapply<<<elem4 / 256, 256>>>(y_, g1, b1, y_, yc_, red_ + 0);

        gemm_mma<<<dim3(8, 125), 128, NG_SMEM>>>(
            yc_, wt_ + wb + OW_1, c1, nullptr, hc_, N_NODES, HID, 768, 1);
        gemm_mma2<<<dim3(1, 125), 256, NG2_SMEM>>>(
            hc_, wt_ + wb + OW_2, c2, out_, N_NODES, DIM, 3072);

        resred<<<elem4 / 256, 256>>>(y_, out_, out_, red_ + 2);
        float* xdst = (blk == 2) ? (float*)d_out : x_;
        lnapply<<<elem4 / 256, 256>>>(out_, g2, b2, xdst, xc_, red_ + 2);

        xcur = x_;
    }
}

// round 10
// speedup vs baseline: 2.8422x; 1.0350x over previous
#include <cuda_runtime.h>
#include <cuda_fp16.h>
#include <math.h>
#include <stdint.h>

#define N_NODES 16000
#define N_EDGES 256000
#define DIM 256
#define HEADS 8
#define HID 1024
#define LN_CNT (N_NODES * DIM)
#define LN_EPS 1e-5f
#define RSQRT_DH 0.17677669529663687f

#define OW_QKVS 0              // [1024, 768]  3-cat
#define OW_E    786432         // [256, 256]   plain fp16
#define OW_1    851968         // [1024, 768]  3-cat
#define OW_2    1638400        // [256, 3072]  3-cat
#define WB      2424832

// ---------------- scratch -----------------------------------------------------
__device__ float    g_qkvs[(size_t)N_NODES * 1024];
__device__ __half   g_e_h3[3 * (size_t)N_EDGES * DIM];   // CSR-ordered
__device__ float    g_out[N_NODES * DIM];
__device__ float    g_y[N_NODES * DIM];
__device__ float    g_x[N_NODES * DIM];
__device__ double   g_red[4];
__device__ float    g_bqkvs[3 * 1024];
__device__ __half   g_xe_h[(size_t)N_EDGES * DIM];       // CSR-ordered gather
__device__ __half   g_x_cat[(size_t)N_NODES * 3 * DIM];
__device__ __half   g_y_cat[(size_t)N_NODES * 3 * DIM];
__device__ __half   g_h_cat[(size_t)N_NODES * 3 * HID];
__device__ __half   g_wt_cat[3 * WB];
// CSR
__device__ int      g_rowstart[N_NODES + 1];
__device__ int      g_cursor[N_NODES];
__device__ int      g_perm[N_EDGES];
__device__ int      g_src_s[N_EDGES];                    // src in CSR order
__device__ float    g_invd_s[N_EDGES];                   // 1/dist in CSR order

// ---------------- helpers -----------------------------------------------------
__device__ __forceinline__ uint32_t smem_u32(const void* p) {
    uint32_t a;
    asm("{ .reg .u64 t; cvta.to.shared.u64 t, %1; cvt.u32.u64 %0, t; }"
        : "=r"(a) : "l"(p));
    return a;
}
__device__ __forceinline__ uint32_t pack_h2(__half a, __half b) {
    __half2 h2 = __halves2half2(a, b);
    return *(uint32_t*)&h2;
}
__device__ __forceinline__ void cp16(uint32_t dst, const void* src) {
    asm volatile("cp.async.cg.shared.global [%0], [%1], 16;"
                 :: "r"(dst), "l"(src) : "memory");
}
__device__ __forceinline__ void ldsm_x4(uint32_t* r, uint32_t addr) {
    asm volatile("ldmatrix.sync.aligned.m8n8.x4.shared.b16 {%0,%1,%2,%3}, [%4];"
                 : "=r"(r[0]), "=r"(r[1]), "=r"(r[2]), "=r"(r[3]) : "r"(addr));
}
__device__ __forceinline__ void mma16816(float* c, const uint32_t* a, uint32_t b0, uint32_t b1) {
    asm volatile(
        "mma.sync.aligned.m16n8k16.row.col.f32.f16.f16.f32 "
        "{%0,%1,%2,%3}, {%4,%5,%6,%7}, {%8,%9}, {%0,%1,%2,%3};"
        : "+f"(c[0]), "+f"(c[1]), "+f"(c[2]), "+f"(c[3])
        : "r"(a[0]), "r"(a[1]), "r"(a[2]), "r"(a[3]), "r"(b0), "r"(b1));
}

// ================== node GEMM 128x128 (4 warps, 3-stage) ======================
#define NG_SMEM 98304

__device__ __forceinline__ void load_chunk_n(
    uint32_t st, const __half* __restrict__ A, const __half* __restrict__ B,
    size_t rowA0, size_t rowB0, int K3, int k0, int tid)
{
#pragma unroll
    for (int i = 0; i < 8; i++) {
        int u = tid + (i << 7);
        int row = u >> 3, kk = u & 7;
        uint32_t off = (uint32_t)(row * 128 + kk * 16);
        uint32_t sw = off ^ ((off >> 3) & 0x70);
        cp16(st + sw, A + (rowA0 + row) * (size_t)K3 + k0 + kk * 8);
        cp16(st + 16384 + sw, B + (rowB0 + row) * (size_t)K3 + k0 + kk * 8);
    }
}

__global__ __launch_bounds__(128) void gemm_mma(
    const __half* __restrict__ A, const __half* __restrict__ B,
    const float* __restrict__ bias,
    float* __restrict__ Cf, __half* __restrict__ Ccat,
    int M, int N, int K3, int relu)
{
    extern __shared__ __align__(128) char smem[];
    uint32_t sbase = smem_u32(smem);

    int tid = threadIdx.x, lane = tid & 31, wid = tid >> 5;
    int warpM = wid >> 1, warpN = wid & 1;
    int tN = blockIdx.x, tM = blockIdx.y;
    size_t rowA0 = (size_t)tM * 128;
    size_t rowB0 = (size_t)tN * 128;
    int nch = K3 >> 6;

    float acc[4][8][4];
#pragma unroll
    for (int i = 0; i < 4; i++)
#pragma unroll
        for (int j = 0; j < 8; j++)
#pragma unroll
            for (int t = 0; t < 4; t++) acc[i][j][t] = 0.f;

    load_chunk_n(sbase, A, B, rowA0, rowB0, K3, 0, tid);
    asm volatile("cp.async.commit_group;" ::: "memory");
    load_chunk_n(sbase + 32768, A, B, rowA0, rowB0, K3, 64, tid);
    asm volatile("cp.async.commit_group;" ::: "memory");

    for (int c = 0; c < nch; c++) {
        if (c + 2 < nch) {
            uint32_t sb = sbase + (uint32_t)((c + 2) % 3) * 32768u;
            load_chunk_n(sb, A, B, rowA0, rowB0, K3, (c + 2) << 6, tid);
            asm volatile("cp.async.commit_group;" ::: "memory");
            asm volatile("cp.async.wait_group 2;" ::: "memory");
        } else if (c + 1 < nch) {
            asm volatile("cp.async.wait_group 1;" ::: "memory");
        } else {
            asm volatile("cp.async.wait_group 0;" ::: "memory");
        }
        __syncthreads();

        uint32_t aB = sbase + (uint32_t)(c % 3) * 32768u;
        uint32_t bB = aB + 16384;
#pragma unroll
        for (int ks = 0; ks < 4; ks++) {
            uint32_t af[4][4], bf[4][4];
#pragma unroll
            for (int mf = 0; mf < 4; mf++) {
                int row = warpM * 64 + mf * 16 + (lane & 15);
                uint32_t off = (uint32_t)(row * 128 + ks * 32 + ((lane >> 4) << 4));
                off ^= (off >> 3) & 0x70;
                ldsm_x4(af[mf], aB + off);
            }
#pragma unroll
            for (int nf2 = 0; nf2 < 4; nf2++) {
                int row = warpN * 64 + nf2 * 16 + (lane & 15);
                uint32_t off = (uint32_t)(row * 128 + ks * 32 + ((lane >> 4) << 4));
                off ^= (off >> 3) & 0x70;
                ldsm_x4(bf[nf2], bB + off);
            }
#pragma unroll
            for (int mf = 0; mf < 4; mf++)
#pragma unroll
                for (int nf2 = 0; nf2 < 4; nf2++) {
                    mma16816(acc[mf][nf2 * 2],     af[mf], bf[nf2][0], bf[nf2][2]);
                    mma16816(acc[mf][nf2 * 2 + 1], af[mf], bf[nf2][1], bf[nf2][3]);
                }
        }
        __syncthreads();
    }

    int m0 = tM * 128 + warpM * 64;
    int n0 = tN * 128 + warpN * 64;
#pragma unroll
    for (int mf = 0; mf < 4; mf++) {
#pragma unroll
        for (int nf = 0; nf < 8; nf++) {
            int r = m0 + mf * 16 + (lane >> 2);
            int col = n0 + nf * 8 + ((lane & 3) << 1);
            float b0 = bias ? __ldg(bias + col) : 0.f;
            float b1 = bias ? __ldg(bias + col + 1) : 0.f;
            float v00 = acc[mf][nf][0] + b0, v01 = acc[mf][nf][1] + b1;
            float v10 = acc[mf][nf][2] + b0, v11 = acc[mf][nf][3] + b1;
            if (relu) {
                v00 = fmaxf(v00, 0.f); v01 = fmaxf(v01, 0.f);
                v10 = fmaxf(v10, 0.f); v11 = fmaxf(v11, 0.f);
            }
            if (Cf) {
                *(float2*)(Cf + (size_t)r * N + col) = make_float2(v00, v01);
                *(float2*)(Cf + (size_t)(r + 8) * N + col) = make_float2(v10, v11);
            }
            if (Ccat) {
                __half h00 = __float2half_rn(v00), h01 = __float2half_rn(v01);
                __half h10 = __float2half_rn(v10), h11 = __float2half_rn(v11);
                uint32_t uh0 = pack_h2(h00, h01), uh1 = pack_h2(h10, h11);
                uint32_t ul0 = pack_h2(__float2half_rn(v00 - __half2float(h00)),
                                       __float2half_rn(v01 - __half2float(h01)));
                uint32_t ul1 = pack_h2(__float2half_rn(v10 - __half2float(h10)),
                                       __float2half_rn(v11 - __half2float(h11)));
                size_t b0a = (size_t)r * 3 * N + col;
                size_t b1a = (size_t)(r + 8) * 3 * N + col;
                *(uint32_t*)(Ccat + b0a) = uh0;
                *(uint32_t*)(Ccat + b0a + N) = ul0;
                *(uint32_t*)(Ccat + b0a + 2 * N) = uh0;
                *(uint32_t*)(Ccat + b1a) = uh1;
                *(uint32_t*)(Ccat + b1a + N) = ul1;
                *(uint32_t*)(Ccat + b1a + 2 * N) = uh1;
            }
        }
    }
}

// ================== node GEMM 128x256 (8 warps, 2-stage) — FFN2 ===============
#define NG2_SMEM 98304

__device__ __forceinline__ void load_chunk_n2(
    uint32_t st, const __half* __restrict__ A, const __half* __restrict__ B,
    size_t rowA0, size_t rowB0, int K3, int k0, int tid)
{
#pragma unroll
    for (int i = 0; i < 4; i++) {
        int u = tid + (i << 8);
        int row = u >> 3, kk = u & 7;
        uint32_t off = (uint32_t)(row * 128 + kk * 16);
        uint32_t sw = off ^ ((off >> 3) & 0x70);
        cp16(st + sw, A + (rowA0 + row) * (size_t)K3 + k0 + kk * 8);
    }
#pragma unroll
    for (int i = 0; i < 8; i++) {
        int u = tid + (i << 8);
        int row = u >> 3, kk = u & 7;
        uint32_t off = (uint32_t)(row * 128 + kk * 16);
        uint32_t sw = off ^ ((off >> 3) & 0x70);
        cp16(st + 16384 + sw, B + (rowB0 + row) * (size_t)K3 + k0 + kk * 8);
    }
}

__global__ __launch_bounds__(256) void gemm_mma2(
    const __half* __restrict__ A, const __half* __restrict__ B,
    const float* __restrict__ bias, float* __restrict__ Cf,
    int M, int N, int K3)
{
    extern __shared__ __align__(128) char smem[];
    uint32_t sbase = smem_u32(smem);

    int tid = threadIdx.x, lane = tid & 31, wid = tid >> 5;
    int warpM = wid >> 2, warpN = wid & 3;
    int tN = blockIdx.x, tM = blockIdx.y;
    size_t rowA0 = (size_t)tM * 128;
    size_t rowB0 = (size_t)tN * 256;
    int nch = K3 >> 6;

    float acc[4][8][4];
#pragma unroll
    for (int i = 0; i < 4; i++)
#pragma unroll
        for (int j = 0; j < 8; j++)
#pragma unroll
            for (int t = 0; t < 4; t++) acc[i][j][t] = 0.f;

    load_chunk_n2(sbase, A, B, rowA0, rowB0, K3, 0, tid);
    asm volatile("cp.async.commit_group;" ::: "memory");

    for (int c = 0; c < nch; c++) {
        if (c + 1 < nch) {
            uint32_t sb = sbase + (uint32_t)((c + 1) & 1) * 49152u;
            load_chunk_n2(sb, A, B, rowA0, rowB0, K3, (c + 1) << 6, tid);
            asm volatile("cp.async.commit_group;" ::: "memory");
            asm volatile("cp.async.wait_group 1;" ::: "memory");
        } else {
            asm volatile("cp.async.wait_group 0;" ::: "memory");
        }
        __syncthreads();

        uint32_t aB = sbase + (uint32_t)(c & 1) * 49152u;
        uint32_t bB = aB + 16384;
#pragma unroll
        for (int ks = 0; ks < 4; ks++) {
            uint32_t af[4][4], bf[4][4];
#pragma unroll
            for (int mf = 0; mf < 4; mf++) {
                int row = warpM * 64 + mf * 16 + (lane & 15);
                uint32_t off = (uint32_t)(row * 128 + ks * 32 + ((lane >> 4) << 4));
                off ^= (off >> 3) & 0x70;
                ldsm_x4(af[mf], aB + off);
            }
#pragma unroll
            for (int nf2 = 0; nf2 < 4; nf2++) {
                int row = warpN * 64 + nf2 * 16 + (lane & 15);
                uint32_t off = (uint32_t)(row * 128 + ks * 32 + ((lane >> 4) << 4));
                off ^= (off >> 3) & 0x70;
                ldsm_x4(bf[nf2], bB + off);
            }
#pragma unroll
            for (int mf = 0; mf < 4; mf++)
#pragma unroll
                for (int nf2 = 0; nf2 < 4; nf2++) {
                    mma16816(acc[mf][nf2 * 2],     af[mf], bf[nf2][0], bf[nf2][2]);
                    mma16816(acc[mf][nf2 * 2 + 1], af[mf], bf[nf2][1], bf[nf2][3]);
                }
        }
        __syncthreads();
    }

    int m0 = tM * 128 + warpM * 64;
    int n0 = tN * 256 + warpN * 64;
#pragma unroll
    for (int mf = 0; mf < 4; mf++) {
#pragma unroll
        for (int nf = 0; nf < 8; nf++) {
            int r = m0 + mf * 16 + (lane >> 2);
            int col = n0 + nf * 8 + ((lane & 3) << 1);
            float b0 = bias ? __ldg(bias + col) : 0.f;
            float b1 = bias ? __ldg(bias + col + 1) : 0.f;
            *(float2*)(Cf + (size_t)r * N + col) =
                make_float2(acc[mf][nf][0] + b0, acc[mf][nf][1] + b1);
            *(float2*)(Cf + (size_t)(r + 8) * N + col) =
                make_float2(acc[mf][nf][2] + b0, acc[mf][nf][3] + b1);
        }
    }
}

// ================== edge GEMM: A-resident, all 3 blocks =======================
#define EG_SMEM 98304

__global__ __launch_bounds__(128) void gemm_edge(
    const __half* __restrict__ XE, const __half* __restrict__ WT,
    __half* __restrict__ EH)
{
    extern __shared__ __align__(128) char smem[];
    uint32_t sbase = smem_u32(smem);
    uint32_t bbase = sbase + 65536;

    int tid = threadIdx.x, lane = tid & 31, wid = tid >> 5;
    int warpM = wid >> 1, warpN = wid & 1;
    size_t rowA0 = (size_t)blockIdx.x * 128;

#pragma unroll
    for (int ch = 0; ch < 4; ch++) {
#pragma unroll
        for (int i = 0; i < 8; i++) {
            int u = tid + (i << 7);
            int row = u >> 3, kk = u & 7;
            uint32_t off = (uint32_t)(row * 128 + kk * 16);
            uint32_t sw = off ^ ((off >> 3) & 0x70);
            cp16(sbase + ch * 16384 + sw, XE + (rowA0 + row) * 256 + ch * 64 + kk * 8);
        }
    }
    {
#pragma unroll
        for (int i = 0; i < 8; i++) {
            int u = tid + (i << 7);
            int row = u >> 3, kk = u & 7;
            uint32_t off = (uint32_t)(row * 128 + kk * 16);
            uint32_t sw = off ^ ((off >> 3) & 0x70);
            cp16(bbase + sw, WT + OW_E + (size_t)row * 256 + kk * 8);
        }
    }
    asm volatile("cp.async.commit_group;" ::: "memory");

    float acc[4][8][4];
#pragma unroll
    for (int i = 0; i < 4; i++)
#pragma unroll
        for (int j = 0; j < 8; j++)
#pragma unroll
            for (int t = 0; t < 4; t++) acc[i][j][t] = 0.f;

    for (int it = 0; it < 24; it++) {
        if (it < 23) {
            int j = it + 1;
            int wt = j >> 2, ck = j & 3;
            int blkj = wt >> 1, nh = wt & 1;
            const __half* Bp = WT + (size_t)blkj * WB + OW_E;
            uint32_t bb = bbase + (uint32_t)(j & 1) * 16384u;
#pragma unroll
            for (int i = 0; i < 8; i++) {
                int u = tid + (i << 7);
                int row = u >> 3, kk = u & 7;
                uint32_t off = (uint32_t)(row * 128 + kk * 16);
                uint32_t sw = off ^ ((off >> 3) & 0x70);
                cp16(bb + sw, Bp + (size_t)(nh * 128 + row) * 256 + ck * 64 + kk * 8);
            }
            asm volatile("cp.async.commit_group;" ::: "memory");
            asm volatile("cp.async.wait_group 1;" ::: "memory");
        } else {
            asm volatile("cp.async.wait_group 0;" ::: "memory");
        }
        __syncthreads();

        int ck = it & 3;
        uint32_t aB = sbase + (uint32_t)ck * 16384u;
        uint32_t bB = bbase + (uint32_t)(it & 1) * 16384u;
#pragma unroll
        for (int ks = 0; ks < 4; ks++) {
            uint32_t af[4][4], bf[4][4];
#pragma unroll
            for (int mf = 0; mf < 4; mf++) {
                int row = warpM * 64 + mf * 16 + (lane & 15);
                uint32_t off = (uint32_t)(row * 128 + ks * 32 + ((lane >> 4) << 4));
                off ^= (off >> 3) & 0x70;
                ldsm_x4(af[mf], aB + off);
            }
#pragma unroll
            for (int nf2 = 0; nf2 < 4; nf2++) {
                int row = warpN * 64 + nf2 * 16 + (lane & 15);
                uint32_t off = (uint32_t)(row * 128 + ks * 32 + ((lane >> 4) << 4));
                off ^= (off >> 3) & 0x70;
                ldsm_x4(bf[nf2], bB + off);
            }
#pragma unroll
            for (int mf = 0; mf < 4; mf++)
#pragma unroll
                for (int nf2 = 0; nf2 < 4; nf2++) {
                    mma16816(acc[mf][nf2 * 2],     af[mf], bf[nf2][0], bf[nf2][2]);
                    mma16816(acc[mf][nf2 * 2 + 1], af[mf], bf[nf2][1], bf[nf2][3]);
                }
        }
        __syncthreads();

        if (ck == 3) {
            int wt = it >> 2;
            int blk = wt >> 1, nh = wt & 1;
            __half* out = EH + (size_t)blk * N_EDGES * DIM;
#pragma unroll
            for (int mf = 0; mf < 4; mf++) {
#pragma unroll
                for (int nf = 0; nf < 8; nf++) {
                    int r = (int)rowA0 + warpM * 64 + mf * 16 + (lane >> 2);
                    int col = nh * 128 + warpN * 64 + nf * 8 + ((lane & 3) << 1);
                    *(__half2*)(out + (size_t)r * DIM + col) =
                        __floats2half2_rn(acc[mf][nf][0], acc[mf][nf][1]);
                    *(__half2*)(out + (size_t)(r + 8) * DIM + col) =
                        __floats2half2_rn(acc[mf][nf][2], acc[mf][nf][3]);
#pragma unroll
                    for (int t = 0; t < 4; t++) acc[mf][nf][t] = 0.f;
                }
            }
        }
    }
}

// ---------------- CSR build ----------------------------------------------------
__global__ void zero_deg() {
    int i = blockIdx.x * blockDim.x + threadIdx.x;
    if (i < N_NODES) g_cursor[i] = 0;
}
__global__ void hist_dst(const int* __restrict__ ei) {
    int i = blockIdx.x * blockDim.x + threadIdx.x;
    if (i < N_EDGES) atomicAdd(&g_cursor[ei[N_EDGES + i]], 1);
}
__global__ __launch_bounds__(1024) void scan16k() {
    __shared__ int warp_tot[32];
    int tid = threadIdx.x, lane = tid & 31, wid = tid >> 5;
    int base = tid * 16;
    int vals[16];
    int s = 0;
#pragma unroll
    for (int t = 0; t < 16; t++) {
        int idx = base + t;
        int v = (idx < N_NODES) ? g_cursor[idx] : 0;
        vals[t] = s;
        s += v;
    }
    int x = s;
#pragma unroll
    for (int o = 1; o < 32; o <<= 1) {
        int n = __shfl_up_sync(0xffffffffu, x, o);
        if (lane >= o) x += n;
    }
    if (lane == 31) warp_tot[wid] = x;
    __syncthreads();
    if (wid == 0) {
        int t = warp_tot[lane];
        int y = t;
#pragma unroll
        for (int o = 1; o < 32; o <<= 1) {
            int n = __shfl_up_sync(0xffffffffu, y, o);
            if (lane >= o) y += n;
        }
        warp_tot[lane] = y - t;
    }
    __syncthreads();
    int offset = warp_tot[wid] + (x - s);
#pragma unroll
    for (int t = 0; t < 16; t++) {
        int idx = base + t;
        if (idx < N_NODES) g_rowstart[idx] = offset + vals[t];
    }
    if (tid == 1023) g_rowstart[N_NODES] = offset + s;
    __syncthreads();
#pragma unroll
    for (int t = 0; t < 16; t++) {
        int idx = base + t;
        if (idx < N_NODES) g_cursor[idx] = g_rowstart[idx];
    }
}
__global__ void scatter_perm(const int* __restrict__ ei,
                             const float* __restrict__ xdist) {
    int i = blockIdx.x * blockDim.x + threadIdx.x;
    if (i < N_EDGES) {
        int d = ei[N_EDGES + i];
        int pos = atomicAdd(&g_cursor[d], 1);
        g_perm[pos] = i;
        g_src_s[pos] = ei[i];
        g_invd_s[pos] = 1.0f / xdist[i];
    }
}

// ---------------- converters / weight prep -------------------------------------
__global__ __launch_bounds__(256) void cvt_cat3(
    const float* __restrict__ s, __half* __restrict__ d, int K, int n4)
{
    int i = blockIdx.x * blockDim.x + threadIdx.x;
    if (i >= n4) return;
    int i4 = i * 4;
    int row = i4 / K, col = i4 % K;
    float4 v = ((const float4*)s)[i];
    float vv[4] = {v.x, v.y, v.z, v.w};
    __half h[4], l[4];
#pragma unroll
    for (int j = 0; j < 4; j++) {
        h[j] = __float2half_rn(vv[j]);
        l[j] = __float2half_rn(vv[j] - __half2float(h[j]));
    }
    size_t base = (size_t)row * 3 * K + col;
    uint2 uh = make_uint2(pack_h2(h[0], h[1]), pack_h2(h[2], h[3]));
    uint2 ul = make_uint2(pack_h2(l[0], l[1]), pack_h2(l[2], l[3]));
    *(uint2*)(d + base) = uh;
    *(uint2*)(d + base + K) = ul;
    *(uint2*)(d + base + 2 * K) = uh;
}

// gathered fp32->fp16: row i of dst = row perm[i] of src (256 cols)
__global__ __launch_bounds__(256) void cvt_h_gather(
    const float* __restrict__ s, __half* __restrict__ d)
{
    // one warp handles half a row (128 cols); 8 warps per CTA -> 4 rows/CTA
    int tid = blockIdx.x * blockDim.x + threadIdx.x;
    int row = tid >> 6;                 // 64 threads per row
    int col = (tid & 63) * 4;
    if (row >= N_EDGES) return;
    int srow = g_perm[row];
    float4 v = *(const float4*)(s + (size_t)srow * DIM + col);
    *(uint2*)(d + (size_t)row * DIM + col) =
        make_uint2(pack_h2(__float2half_rn(v.x), __float2half_rn(v.y)),
                   pack_h2(__float2half_rn(v.z), __float2half_rn(v.w)));
}

__global__ void tconv(const float* __restrict__ W, __half* __restrict__ out,
                      int K, int N, int cat)
{
    __shared__ float t[32][33];
    int tx = threadIdx.x, ty = threadIdx.y;
    int n0 = blockIdx.x * 32, k0 = blockIdx.y * 32;
#pragma unroll
    for (int r = 0; r < 4; r++)
        t[ty + 8 * r][tx] = W[(size_t)(k0 + ty + 8 * r) * N + n0 + tx];
    __syncthreads();
    int stride = cat * K;
#pragma unroll
    for (int r = 0; r < 4; r++) {
        int nl = ty + 8 * r;
        float v = t[tx][nl];
        size_t o = (size_t)(n0 + nl) * stride + k0 + tx;
        __half h = __float2half_rn(v);
        out[o] = h;
        if (cat == 3) {
            out[o + K] = h;
            out[o + 2 * K] = __float2half_rn(v - __half2float(h));
        }
    }
}

__global__ void pack_bias(const float* __restrict__ bq, const float* __restrict__ bk,
                          const float* __restrict__ bv, const float* __restrict__ bs)
{
    int b = blockIdx.x, t = threadIdx.x;
    float v = (t < 256) ? bq[b * 256 + t]
            : (t < 512) ? bk[b * 256 + t - 256]
            : (t < 768) ? bv[b * 256 + t - 512]
                        : bs[b * 256 + t - 768];
    g_bqkvs[b * 1024 + t] = v;
}

__global__ void zero_red() {
    if (threadIdx.x < 4) g_red[threadIdx.x] = 0.0;
}

// ---------------- fused CSR attention + skip + residual + LN reduction ---------
// one warp per destination node; all edge-side arrays sequential in CSR order
__global__ __launch_bounds__(256) void attn_csr(
    const __half* __restrict__ eh, const float* __restrict__ x,
    float* __restrict__ y, double* __restrict__ red)
{
    int tid = threadIdx.x, lane = tid & 31, wid = tid >> 5;
    int node = blockIdx.x * 8 + wid;

    double ls = 0.0, lq = 0.0;
    if (node < N_NODES) {
        const float* qrow = g_qkvs + (size_t)node * 1024;
        float4 q0 = *(const float4*)(qrow + lane * 8);
        float4 q1 = *(const float4*)(qrow + lane * 8 + 4);

        int start = g_rowstart[node];
        int end   = g_rowstart[node + 1];

        float m0 = 0.f, m1 = 0.f, m2 = 0.f, m3 = 0.f;
        float m4 = 0.f, m5 = 0.f, m6 = 0.f, m7 = 0.f;
        float denom = 0.f;

        for (int j = start; j < end; j++) {
            int src = g_src_s[j];
            float invd = g_invd_s[j];

            const float* krow = g_qkvs + (size_t)src * 1024 + 256;
            const float* vrow = g_qkvs + (size_t)src * 1024 + 512;
            float4 k0 = *(const float4*)(krow + lane * 8);
            float4 k1 = *(const float4*)(krow + lane * 8 + 4);
            int4 evi = *(const int4*)(eh + (size_t)j * DIM + lane * 8);
            __half2* ehp = (__half2*)&evi;
            float2 e0 = __half22float2(ehp[0]), e1 = __half22float2(ehp[1]);
            float2 e2 = __half22float2(ehp[2]), e3 = __half22float2(ehp[3]);

            float p = 0.f;
            p = fmaf(q0.x, k0.x + e0.x, p);
            p = fmaf(q0.y, k0.y + e0.y, p);
            p = fmaf(q0.z, k0.z + e1.x, p);
            p = fmaf(q0.w, k0.w + e1.y, p);
            p = fmaf(q1.x, k1.x + e2.x, p);
            p = fmaf(q1.y, k1.y + e2.y, p);
            p = fmaf(q1.z, k1.z + e3.x, p);
            p = fmaf(q1.w, k1.w + e3.y, p);
            p += __shfl_xor_sync(0xffffffffu, p, 1);
            p += __shfl_xor_sync(0xffffffffu, p, 2);

            float ex = __expf(p * invd * RSQRT_DH);
            denom += ex;

            float4 v0 = *(const float4*)(vrow + lane * 8);
            float4 v1 = *(const float4*)(vrow + lane * 8 + 4);
            m0 = fmaf(v0.x + e0.x, ex, m0);
            m1 = fmaf(v0.y + e0.y, ex, m1);
            m2 = fmaf(v0.z + e1.x, ex, m2);
            m3 = fmaf(v0.w + e1.y, ex, m3);
            m4 = fmaf(v1.x + e2.x, ex, m4);
            m5 = fmaf(v1.y + e2.y, ex, m5);
            m6 = fmaf(v1.z + e3.x, ex, m6);
            m7 = fmaf(v1.w + e3.y, ex, m7);
        }

        float inv = 1.0f / (denom + 1e-16f);
        const float* xr = x + (size_t)node * 256 + lane * 8;
        const float* sk = g_qkvs + (size_t)node * 1024 + 768 + lane * 8;
        float4 xv0 = *(const float4*)(xr);
        float4 xv1 = *(const float4*)(xr + 4);
        float4 sk0 = *(const float4*)(sk);
        float4 sk1 = *(const float4*)(sk + 4);

        float r0 = xv0.x + sk0.x + m0 * inv;
        float r1 = xv0.y + sk0.y + m1 * inv;
        float r2 = xv0.z + sk0.z + m2 * inv;
        float r3 = xv0.w + sk0.w + m3 * inv;
        float r4 = xv1.x + sk1.x + m4 * inv;
        float r5 = xv1.y + sk1.y + m5 * inv;
        float r6 = xv1.z + sk1.z + m6 * inv;
        float r7 = xv1.w + sk1.w + m7 * inv;

        float* yp = y + (size_t)node * 256 + lane * 8;
        *(float4*)(yp)     = make_float4(r0, r1, r2, r3);
        *(float4*)(yp + 4) = make_float4(r4, r5, r6, r7);

        ls = (double)r0 + (double)r1 + (double)r2 + (double)r3 +
             (double)r4 + (double)r5 + (double)r6 + (double)r7;
        lq = (double)r0 * r0 + (double)r1 * r1 + (double)r2 * r2 + (double)r3 * r3 +
             (double)r4 * r4 + (double)r5 * r5 + (double)r6 * r6 + (double)r7 * r7;
    }

#pragma unroll
    for (int o = 16; o > 0; o >>= 1) {
        ls += __shfl_down_sync(0xffffffffu, ls, o);
        lq += __shfl_down_sync(0xffffffffu, lq, o);
    }
    __shared__ double shs[8], shq[8];
    if (lane == 0) { shs[wid] = ls; shq[wid] = lq; }
    __syncthreads();
    if (tid == 0) {
        double ts = 0, tq = 0;
#pragma unroll
        for (int k = 0; k < 8; k++) { ts += shs[k]; tq += shq[k]; }
        atomicAdd(&red[0], ts);
        atomicAdd(&red[1], tq);
    }
}

// ---------------- plain residual + DP reduction --------------------------------
__global__ __launch_bounds__(256) void resred(
    const float* __restrict__ a, const float* __restrict__ b,
    float* __restrict__ y, double* __restrict__ red)
{
    int i = blockIdx.x * blockDim.x + threadIdx.x;
    float4 av = ((const float4*)a)[i];
    float4 bv = ((const float4*)b)[i];
    float4 s = make_float4(av.x + bv.x, av.y + bv.y, av.z + bv.z, av.w + bv.w);
    ((float4*)y)[i] = s;

    double ls = (double)s.x + (double)s.y + (double)s.z + (double)s.w;
    double lq = (double)s.x * s.x + (double)s.y * s.y +
                (double)s.z * s.z + (double)s.w * s.w;
#pragma unroll
    for (int o = 16; o > 0; o >>= 1) {
        ls += __shfl_down_sync(0xffffffffu, ls, o);
        lq += __shfl_down_sync(0xffffffffu, lq, o);
    }
    __shared__ double shs[8], shq[8];
    int wid = threadIdx.x >> 5, lane = threadIdx.x & 31;
    if (lane == 0) { shs[wid] = ls; shq[wid] = lq; }
    __syncthreads();
    if (threadIdx.x == 0) {
        double ts = 0, tq = 0;
#pragma unroll
        for (int k = 0; k < 8; k++) { ts += shs[k]; tq += shq[k]; }
        atomicAdd(&red[0], ts);
        atomicAdd(&red[1], tq);
    }
}

// ---------------- graph layernorm apply + 3-cat fp16 emit ----------------------
__global__ __launch_bounds__(256) void lnapply(
    const float* __restrict__ y, const float* __restrict__ g,
    const float* __restrict__ b, float* __restrict__ o,
    __half* __restrict__ ocat, const double* __restrict__ red)
{
    int i = blockIdx.x * blockDim.x + threadIdx.x;
    double mean = red[0] / (double)LN_CNT;
    double var  = red[1] / (double)LN_CNT - mean * mean;
    if (var < 0) var = 0;
    float inv = 1.0f / ((float)sqrt(var) + LN_EPS);
    float mu = (float)mean;

    int i4 = i * 4;
    int c = i4 % DIM;
    int row = i4 / DIM;
    float4 yv = ((const float4*)y)[i];
    float4 gv = *(const float4*)(g + c);
    float4 bv = *(const float4*)(b + c);
    float4 r;
    r.x = (yv.x - mu) * inv * gv.x + bv.x;
    r.y = (yv.y - mu) * inv * gv.y + bv.y;
    r.z = (yv.z - mu) * inv * gv.z + bv.z;
    r.w = (yv.w - mu) * inv * gv.w + bv.w;
    ((float4*)o)[i] = r;

    float vv[4] = {r.x, r.y, r.z, r.w};
    __half h[4], l[4];
#pragma unroll
    for (int j = 0; j < 4; j++) {
        h[j] = __float2half_rn(vv[j]);
        l[j] = __float2half_rn(vv[j] - __half2float(h[j]));
    }
    size_t base = (size_t)row * 3 * DIM + c;
    uint2 uh = make_uint2(pack_h2(h[0], h[1]), pack_h2(h[2], h[3]));
    uint2 ul = make_uint2(pack_h2(l[0], l[1]), pack_h2(l[2], l[3]));
    *(uint2*)(ocat + base) = uh;
    *(uint2*)(ocat + base + DIM) = ul;
    *(uint2*)(ocat + base + 2 * DIM) = uh;
}

// ---------------- host orchestration -------------------------------------------
extern "C" void kernel_launch(void* const* d_in, const int* in_sizes, int n_in,
                              void* d_out, int out_size)
{
    const float* x_in   = (const float*)d_in[0];
    const int*   ei     = (const int*)d_in[1];
    const float* x_edge = (const float*)d_in[2];
    const float* x_dist = (const float*)d_in[3];
    const float* Wq_a   = (const float*)d_in[4];
    const float* bq_a   = (const float*)d_in[5];
    const float* Wk_a   = (const float*)d_in[6];
    const float* bk_a   = (const float*)d_in[7];
    const float* Wv_a   = (const float*)d_in[8];
    const float* bv_a   = (const float*)d_in[9];
    const float* We_a   = (const float*)d_in[10];
    const float* Ws_a   = (const float*)d_in[11];
    const float* bs_a   = (const float*)d_in[12];
    const float* g1_a   = (const float*)d_in[13];
    const float* b1_a   = (const float*)d_in[14];
    const float* W1_a   = (const float*)d_in[15];
    const float* c1_a   = (const float*)d_in[16];
    const float* W2_a   = (const float*)d_in[17];
    const float* c2_a   = (const float*)d_in[18];
    const float* g2_a   = (const float*)d_in[19];
    const float* b2_a   = (const float*)d_in[20];

    static int smem_set = 0;
    if (!smem_set) {
        cudaFuncSetAttribute(gemm_mma, cudaFuncAttributeMaxDynamicSharedMemorySize, NG_SMEM);
        cudaFuncSetAttribute(gemm_mma2, cudaFuncAttributeMaxDynamicSharedMemorySize, NG2_SMEM);
        cudaFuncSetAttribute(gemm_edge, cudaFuncAttributeMaxDynamicSharedMemorySize, EG_SMEM);
        smem_set = 1;
    }

    float *qkvs_, *out_, *y_, *x_, *bqkvs_;
    double* red_;
    __half *eh3_, *xeh_, *xc_, *yc_, *hc_, *wt_;
    cudaGetSymbolAddress((void**)&qkvs_, g_qkvs);
    cudaGetSymbolAddress((void**)&eh3_,  g_e_h3);
    cudaGetSymbolAddress((void**)&out_,  g_out);
    cudaGetSymbolAddress((void**)&y_,    g_y);
    cudaGetSymbolAddress((void**)&x_,    g_x);
    cudaGetSymbolAddress((void**)&red_,  g_red);
    cudaGetSymbolAddress((void**)&bqkvs_, g_bqkvs);
    cudaGetSymbolAddress((void**)&xeh_,  g_xe_h);
    cudaGetSymbolAddress((void**)&xc_,   g_x_cat);
    cudaGetSymbolAddress((void**)&yc_,   g_y_cat);
    cudaGetSymbolAddress((void**)&hc_,   g_h_cat);
    cudaGetSymbolAddress((void**)&wt_,   g_wt_cat);

    const int elem4 = LN_CNT / 4;

    // CSR build first (perm needed by the gathering converter)
    zero_deg<<<(N_NODES + 255) / 256, 256>>>();
    hist_dst<<<(N_EDGES + 255) / 256, 256>>>(ei);
    scan16k<<<1, 1024>>>();
    scatter_perm<<<(N_EDGES + 255) / 256, 256>>>(ei, x_dist);

    // conversions + weight prep
    cvt_cat3<<<(elem4 + 255) / 256, 256>>>(x_in, xc_, DIM, elem4);
    cvt_h_gather<<<(N_EDGES * 64) / 256, 256>>>(x_edge, xeh_);
    pack_bias<<<3, 1024>>>(bq_a, bk_a, bv_a, bs_a);
    dim3 tb(32, 8);
    for (int b = 0; b < 3; b++) {
        size_t wb = (size_t)b * WB;
        __half* wq = wt_ + wb + OW_QKVS;
        tconv<<<dim3(8, 8),  tb>>>(Wq_a + (size_t)b * DIM * DIM, wq,             DIM, DIM, 3);
        tconv<<<dim3(8, 8),  tb>>>(Wk_a + (size_t)b * DIM * DIM, wq + 256 * 768, DIM, DIM, 3);
        tconv<<<dim3(8, 8),  tb>>>(Wv_a + (size_t)b * DIM * DIM, wq + 512 * 768, DIM, DIM, 3);
        tconv<<<dim3(8, 8),  tb>>>(Ws_a + (size_t)b * DIM * DIM, wq + 768 * 768, DIM, DIM, 3);
        tconv<<<dim3(8, 8),  tb>>>(We_a + (size_t)b * DIM * DIM, wt_ + wb + OW_E, DIM, DIM, 1);
        tconv<<<dim3(32, 8), tb>>>(W1_a + (size_t)b * DIM * HID, wt_ + wb + OW_1, DIM, HID, 3);
        tconv<<<dim3(8, 32), tb>>>(W2_a + (size_t)b * HID * DIM, wt_ + wb + OW_2, HID, DIM, 3);
    }

    // edge projections for all blocks, output already CSR-ordered
    gemm_edge<<<N_EDGES / 128, 128, EG_SMEM>>>(xeh_, wt_, eh3_);

    const float* xcur = x_in;
    for (int blk = 0; blk < 3; blk++) {
        size_t wb = (size_t)blk * WB;
        const float* g1 = g1_a + blk * DIM;
        const float* b1 = b1_a + blk * DIM;
        const float* c1 = c1_a + blk * HID;
        const float* c2 = c2_a + blk * DIM;
        const float* g2 = g2_a + blk * DIM;
        const float* b2 = b2_a + blk * DIM;

        zero_red<<<1, 32>>>();

        gemm_mma<<<dim3(8, 125), 128, NG_SMEM>>>(
            xc_, wt_ + wb + OW_QKVS, bqkvs_ + blk * 1024,
            qkvs_, nullptr, N_NODES, 1024, 768, 0);

        attn_csr<<<N_NODES / 8, 256>>>(eh3_ + (size_t)blk * N_EDGES * DIM,
                                       xcur, y_, red_ + 0);
        lnapply<<<elem4 / 256, 256>>>(y_, g1, b1, y_, yc_, red_ + 0);

        gemm_mma<<<dim3(8, 125), 128, NG_SMEM>>>(
            yc_, wt_ + wb + OW_1, c1, nullptr, hc_, N_NODES, HID, 768, 1);
        gemm_mma2<<<dim3(1, 125), 256, NG2_SMEM>>>(
            hc_, wt_ + wb + OW_2, c2, out_, N_NODES, DIM, 3072);

        resred<<<elem4 / 256, 256>>>(y_, out_, out_, red_ + 2);
        float* xdst = (blk == 2) ? (float*)d_out : x_;
        lnapply<<<elem4 / 256, 256>>>(out_, g2, b2, xdst, xc_, red_ + 2);

        xcur = x_;
    }
}